// round 4
// baseline (speedup 1.0000x reference)
#include <cuda_runtime.h>
#include <math.h>

#define Bq 8
#define Tq 2048
#define Cq 1024
#define Hq 16
#define Nq 64
#define FFNq 3584
#define EPSq 1e-5f
#define ROWS (Bq*Tq)            // 16384

// ---------------- scratch (device globals; no cudaMalloc allowed) -----------
__device__ float g_x0 [ROWS*Cq];
__device__ float g_xn [ROWS*Cq];
__device__ float g_xk [ROWS*Cq];
__device__ float g_xv [ROWS*Cq];
__device__ float g_xr [ROWS*Cq];
__device__ float g_xg [ROWS*Cq];
__device__ float g_r  [ROWS*Cq];
__device__ float g_k  [ROWS*Cq];
__device__ float g_v  [ROWS*Cq];
__device__ float g_g  [ROWS*Cq];
__device__ float g_y  [ROWS*Cq];
__device__ float g_z  [ROWS*Cq];
__device__ float g_x1 [ROWS*Cq];
__device__ float g_kv [ROWS*Cq];
__device__ float g_kf [(size_t)ROWS*FFNq];

// ---------------- block reduce (sum pair) over 256 threads ------------------
__device__ __forceinline__ void block_reduce_2(float& a, float& b) {
    __shared__ float sa[8], sb[8];
    int lane = threadIdx.x & 31, wid = threadIdx.x >> 5;
    #pragma unroll
    for (int o = 16; o > 0; o >>= 1) {
        a += __shfl_xor_sync(0xffffffffu, a, o);
        b += __shfl_xor_sync(0xffffffffu, b, o);
    }
    if (lane == 0) { sa[wid] = a; sb[wid] = b; }
    __syncthreads();
    a = 0.f; b = 0.f;
    #pragma unroll
    for (int i = 0; i < 8; i++) { a += sa[i]; b += sb[i]; }
    __syncthreads();   // safe for back-to-back calls
}

// ---------------- fused ln0 + ln1 -------------------------------------------
__global__ void ln01_kernel(const float* __restrict__ x,
                            const float* __restrict__ w0, const float* __restrict__ b0,
                            const float* __restrict__ w1, const float* __restrict__ b1,
                            float* __restrict__ x0, float* __restrict__ xn) {
    int row = blockIdx.x, tid = threadIdx.x;
    size_t off = (size_t)row * Cq;
    float v[4];
    float s = 0.f, s2 = 0.f;
    #pragma unroll
    for (int i = 0; i < 4; i++) {
        v[i] = x[off + tid + i*256];
        s += v[i]; s2 += v[i]*v[i];
    }
    block_reduce_2(s, s2);
    float mu = s * (1.f/Cq);
    float inv = rsqrtf(s2*(1.f/Cq) - mu*mu + EPSq);
    float o[4];
    s = 0.f; s2 = 0.f;
    #pragma unroll
    for (int i = 0; i < 4; i++) {
        int c = tid + i*256;
        o[i] = (v[i]-mu)*inv*w0[c] + b0[c];
        x0[off + c] = o[i];
        s += o[i]; s2 += o[i]*o[i];
    }
    block_reduce_2(s, s2);
    mu = s * (1.f/Cq);
    inv = rsqrtf(s2*(1.f/Cq) - mu*mu + EPSq);
    #pragma unroll
    for (int i = 0; i < 4; i++) {
        int c = tid + i*256;
        xn[off + c] = (o[i]-mu)*inv*w1[c] + b1[c];
    }
}

// ---------------- plain layernorm -------------------------------------------
__global__ void ln_kernel(const float* __restrict__ x,
                          const float* __restrict__ w, const float* __restrict__ b,
                          float* __restrict__ out) {
    int row = blockIdx.x, tid = threadIdx.x;
    size_t off = (size_t)row * Cq;
    float v[4]; float s = 0.f, s2 = 0.f;
    #pragma unroll
    for (int i = 0; i < 4; i++) {
        v[i] = x[off + tid + i*256];
        s += v[i]; s2 += v[i]*v[i];
    }
    block_reduce_2(s, s2);
    float mu = s * (1.f/Cq);
    float inv = rsqrtf(s2*(1.f/Cq) - mu*mu + EPSq);
    #pragma unroll
    for (int i = 0; i < 4; i++) {
        int c = tid + i*256;
        out[off + c] = (v[i]-mu)*inv*w[c] + b[c];
    }
}

// ---------------- token-shift mixes -----------------------------------------
__global__ void mix4_kernel(const float* __restrict__ xn,
                            const float* __restrict__ tmk, const float* __restrict__ tmv,
                            const float* __restrict__ tmr, const float* __restrict__ tmg,
                            float* __restrict__ xk, float* __restrict__ xv,
                            float* __restrict__ xr, float* __restrict__ xg) {
    int row = blockIdx.x, tid = threadIdx.x;
    int t = row & (Tq-1);
    size_t off = (size_t)row * Cq;
    #pragma unroll
    for (int i = 0; i < 4; i++) {
        int c = tid + i*256;
        float cur = xn[off + c];
        float prv = (t > 0) ? xn[off - Cq + c] : 0.f;
        float mk = tmk[c], mv = tmv[c], mr = tmr[c], mg = tmg[c];
        xk[off+c] = cur*mk + prv*(1.f-mk);
        xv[off+c] = cur*mv + prv*(1.f-mv);
        xr[off+c] = cur*mr + prv*(1.f-mr);
        xg[off+c] = cur*mg + prv*(1.f-mg);
    }
}

__global__ void mix2_kernel(const float* __restrict__ xn,
                            const float* __restrict__ tmk, const float* __restrict__ tmr,
                            float* __restrict__ xk, float* __restrict__ xr) {
    int row = blockIdx.x, tid = threadIdx.x;
    int t = row & (Tq-1);
    size_t off = (size_t)row * Cq;
    #pragma unroll
    for (int i = 0; i < 4; i++) {
        int c = tid + i*256;
        float cur = xn[off + c];
        float prv = (t > 0) ? xn[off - Cq + c] : 0.f;
        float mk = tmk[c], mr = tmr[c];
        xk[off+c] = cur*mk + prv*(1.f-mk);
        xr[off+c] = cur*mr + prv*(1.f-mr);
    }
}

// ---------------- NT SGEMM: out[m][n] = epi( sum_k A[m][k]*W[n][k] ) --------
// EPI: 0 plain, 1 res+acc, 2 relu(acc)^2, 3 res + sigmoid(acc)*aux
#define TBM 128
#define TBN 128
#define TBK 16
template<int EPI>
__global__ __launch_bounds__(256)
void gemm_nt(const float* __restrict__ A, const float* __restrict__ W,
             float* __restrict__ out, int M, int N, int K,
             const float* __restrict__ res, const float* __restrict__ aux) {
    __shared__ float As[TBK][TBM+4];
    __shared__ float Ws[TBK][TBN+4];
    int tid = threadIdx.x;
    int bm = blockIdx.y * TBM;
    int bn = blockIdx.x * TBN;
    int tx = tid & 15, ty = tid >> 4;

    float acc[8][8];
    #pragma unroll
    for (int i = 0; i < 8; i++)
        #pragma unroll
        for (int j = 0; j < 8; j++) acc[i][j] = 0.f;

    for (int k0 = 0; k0 < K; k0 += TBK) {
        #pragma unroll
        for (int l = 0; l < 8; l++) {
            int idx = tid + l*256;
            int m = idx >> 4, kk = idx & 15;
            As[kk][m] = A[(size_t)(bm+m)*K + k0 + kk];
        }
        #pragma unroll
        for (int l = 0; l < 8; l++) {
            int idx = tid + l*256;
            int n = idx >> 4, kk = idx & 15;
            Ws[kk][n] = W[(size_t)(bn+n)*K + k0 + kk];
        }
        __syncthreads();
        #pragma unroll
        for (int k = 0; k < TBK; k++) {
            float a[8], b[8];
            #pragma unroll
            for (int i = 0; i < 4; i++) {
                a[i]   = As[k][ty*4+i];
                a[4+i] = As[k][64+ty*4+i];
                b[i]   = Ws[k][tx*4+i];
                b[4+i] = Ws[k][64+tx*4+i];
            }
            #pragma unroll
            for (int i = 0; i < 8; i++)
                #pragma unroll
                for (int j = 0; j < 8; j++)
                    acc[i][j] = fmaf(a[i], b[j], acc[i][j]);
        }
        __syncthreads();
    }
    #pragma unroll
    for (int i = 0; i < 8; i++) {
        int m = bm + ((i < 4) ? (ty*4+i) : (64 + ty*4 + (i-4)));
        #pragma unroll
        for (int j = 0; j < 8; j++) {
            int n = bn + ((j < 4) ? (tx*4+j) : (64 + tx*4 + (j-4)));
            size_t idx = (size_t)m * N + n;
            float v = acc[i][j];
            if (EPI == 0) out[idx] = v;
            else if (EPI == 1) out[idx] = res[idx] + v;
            else if (EPI == 2) { float t = fmaxf(v, 0.f); out[idx] = t*t; }
            else { float sg = 1.f/(1.f + expf(-v)); out[idx] = res[idx] + sg*aux[idx]; }
        }
    }
}

// ---------------- wkv5 recurrence -------------------------------------------
// y_j = sum_i r_i*S_ij + (sum_i r_i*u_i*k_i)*v_j ; S_ij = ew_i*S_ij + k_i*v_j
__global__ __launch_bounds__(256)
void wkv5_kernel(const float* __restrict__ r, const float* __restrict__ k,
                 const float* __restrict__ v, const float* __restrict__ w,
                 const float* __restrict__ u, float* __restrict__ y) {
    int bh = blockIdx.x;
    int b = bh >> 4, h = bh & 15;
    int tid = threadIdx.x;
    int j = tid >> 2, q = tid & 3, i0 = q * 16;

    __shared__ float rs[64], ks[64], vs[64], us[64], csh;
    if (tid < 64) us[tid] = u[h*64 + tid];

    float s[16], ew[16];
    #pragma unroll
    for (int ii = 0; ii < 16; ii++) {
        s[ii] = 0.f;
        ew[ii] = expf(-expf(w[h*64 + i0 + ii]));
    }
    __syncthreads();

    size_t base = (size_t)b * Tq * Cq + h * 64;
    for (int t = 0; t < Tq; t++) {
        size_t off = base + (size_t)t * Cq;
        if (tid < 64)       rs[tid]      = r[off + tid];
        else if (tid < 128) ks[tid-64]   = k[off + tid - 64];
        else if (tid < 192) vs[tid-128]  = v[off + tid - 128];
        __syncthreads();
        if (tid < 32) {
            float p = rs[tid]*us[tid]*ks[tid] + rs[tid+32]*us[tid+32]*ks[tid+32];
            #pragma unroll
            for (int o = 16; o > 0; o >>= 1) p += __shfl_xor_sync(0xffffffffu, p, o);
            if (tid == 0) csh = p;
        }
        __syncthreads();
        float vj = vs[j];
        float yp = 0.f;
        #pragma unroll
        for (int ii = 0; ii < 16; ii++) {
            yp = fmaf(rs[i0+ii], s[ii], yp);
            s[ii] = fmaf(ew[ii], s[ii], ks[i0+ii]*vj);
        }
        yp += __shfl_xor_sync(0xffffffffu, yp, 1);
        yp += __shfl_xor_sync(0xffffffffu, yp, 2);
        if (q == 0) y[off + j] = yp + csh * vj;
        __syncthreads();
    }
}

// ---------------- groupnorm(y/8)*silu(g) ------------------------------------
__global__ void gngate_kernel(const float* __restrict__ y, const float* __restrict__ g,
                              const float* __restrict__ w, const float* __restrict__ b,
                              float* __restrict__ z) {
    int idx = blockIdx.x;              // row*H + h
    int h = idx & (Hq-1);
    size_t off = (size_t)(idx >> 4) * Cq + h * 64;
    int lane = threadIdx.x;
    float y0 = y[off + lane]      * 0.125f;
    float y1 = y[off + lane + 32] * 0.125f;
    float s = y0 + y1, s2 = y0*y0 + y1*y1;
    #pragma unroll
    for (int o = 16; o > 0; o >>= 1) {
        s  += __shfl_xor_sync(0xffffffffu, s, o);
        s2 += __shfl_xor_sync(0xffffffffu, s2, o);
    }
    float mu = s * (1.f/64.f);
    float inv = rsqrtf(s2*(1.f/64.f) - mu*mu + EPSq);
    int c0 = h*64 + lane;
    float g0 = g[off + lane];
    float g1 = g[off + lane + 32];
    float si0 = g0 / (1.f + expf(-g0));
    float si1 = g1 / (1.f + expf(-g1));
    z[off + lane]      = ((y0-mu)*inv*w[c0]    + b[c0])    * si0;
    z[off + lane + 32] = ((y1-mu)*inv*w[c0+32] + b[c0+32]) * si1;
}

// ---------------- launch ----------------------------------------------------
extern "C" void kernel_launch(void* const* d_in, const int* in_sizes, int n_in,
                              void* d_out, int out_size) {
    const float* x        = (const float*)d_in[0];
    const float* ln0_w    = (const float*)d_in[1];
    const float* ln0_b    = (const float*)d_in[2];
    const float* ln1_w    = (const float*)d_in[3];
    const float* ln1_b    = (const float*)d_in[4];
    const float* ln2_w    = (const float*)d_in[5];
    const float* ln2_b    = (const float*)d_in[6];
    const float* att_tmk  = (const float*)d_in[7];
    const float* att_tmv  = (const float*)d_in[8];
    const float* att_tmr  = (const float*)d_in[9];
    const float* att_tmg  = (const float*)d_in[10];
    const float* att_decay= (const float*)d_in[11];
    const float* att_faaaa= (const float*)d_in[12];
    const float* att_Wr   = (const float*)d_in[13];
    const float* att_Wk   = (const float*)d_in[14];
    const float* att_Wv   = (const float*)d_in[15];
    const float* att_Wg   = (const float*)d_in[16];
    const float* att_Wo   = (const float*)d_in[17];
    const float* lnx_w    = (const float*)d_in[18];
    const float* lnx_b    = (const float*)d_in[19];
    const float* ffn_tmk  = (const float*)d_in[20];
    const float* ffn_tmr  = (const float*)d_in[21];
    const float* ffn_Wk   = (const float*)d_in[22];
    const float* ffn_Wr   = (const float*)d_in[23];
    const float* ffn_Wv   = (const float*)d_in[24];
    float* out = (float*)d_out;

    float *x0, *xn, *xk, *xv, *xr, *xg, *r_, *k_, *v_, *g_, *y_, *z_, *x1, *kv, *kf;
    cudaGetSymbolAddress((void**)&x0, g_x0);
    cudaGetSymbolAddress((void**)&xn, g_xn);
    cudaGetSymbolAddress((void**)&xk, g_xk);
    cudaGetSymbolAddress((void**)&xv, g_xv);
    cudaGetSymbolAddress((void**)&xr, g_xr);
    cudaGetSymbolAddress((void**)&xg, g_xg);
    cudaGetSymbolAddress((void**)&r_, g_r);
    cudaGetSymbolAddress((void**)&k_, g_k);
    cudaGetSymbolAddress((void**)&v_, g_v);
    cudaGetSymbolAddress((void**)&g_, g_g);
    cudaGetSymbolAddress((void**)&y_, g_y);
    cudaGetSymbolAddress((void**)&z_, g_z);
    cudaGetSymbolAddress((void**)&x1, g_x1);
    cudaGetSymbolAddress((void**)&kv, g_kv);
    cudaGetSymbolAddress((void**)&kf, g_kf);

    dim3 blk256(256);
    dim3 gCC(Cq/TBN, ROWS/TBM);       // (8, 128)
    dim3 gCF(FFNq/TBN, ROWS/TBM);     // (28, 128)

    // 1) ln0 + ln1
    ln01_kernel<<<ROWS, blk256>>>(x, ln0_w, ln0_b, ln1_w, ln1_b, x0, xn);
    // 2) token-shift mixes (attention)
    mix4_kernel<<<ROWS, blk256>>>(xn, att_tmk, att_tmv, att_tmr, att_tmg, xk, xv, xr, xg);
    // 3) projections
    gemm_nt<0><<<gCC, blk256>>>(xr, att_Wr, r_, ROWS, Cq, Cq, nullptr, nullptr);
    gemm_nt<0><<<gCC, blk256>>>(xk, att_Wk, k_, ROWS, Cq, Cq, nullptr, nullptr);
    gemm_nt<0><<<gCC, blk256>>>(xv, att_Wv, v_, ROWS, Cq, Cq, nullptr, nullptr);
    gemm_nt<0><<<gCC, blk256>>>(xg, att_Wg, g_, ROWS, Cq, Cq, nullptr, nullptr);
    // 4) wkv5 recurrence
    wkv5_kernel<<<Bq*Hq, blk256>>>(r_, k_, v_, att_decay, att_faaaa, y_);
    // 5) groupnorm + gate
    gngate_kernel<<<ROWS*Hq, 32>>>(y_, g_, lnx_w, lnx_b, z_);
    // 6) output projection + residual
    gemm_nt<1><<<gCC, blk256>>>(z_, att_Wo, x1, ROWS, Cq, Cq, x0, nullptr);
    // 7) channel-mix
    ln_kernel<<<ROWS, blk256>>>(x1, ln2_w, ln2_b, xn);
    mix2_kernel<<<ROWS, blk256>>>(xn, ffn_tmk, ffn_tmr, xk, xr);
    gemm_nt<2><<<gCF, blk256>>>(xk, ffn_Wk, kf, ROWS, FFNq, Cq, nullptr, nullptr);
    gemm_nt<0><<<gCC, blk256>>>(kf, ffn_Wv, kv, ROWS, Cq, FFNq, nullptr, nullptr);
    gemm_nt<3><<<gCC, blk256>>>(xr, ffn_Wr, out, ROWS, Cq, Cq, x1, kv);
}

// round 9
// speedup vs baseline: 2.1024x; 2.1024x over previous
#include <cuda_runtime.h>
#include <cuda_bf16.h>
#include <cstdint>
#include <math.h>

#define Bq 8
#define Tq 2048
#define Cq 1024
#define Hq 16
#define Nq 64
#define FFNq 3584
#define EPSq 1e-5f
#define ROWS (Bq*Tq)            // 16384

// ---------------- scratch (device globals; no cudaMalloc allowed) -----------
__device__ __align__(16) float g_x0 [ROWS*Cq];
__device__ __align__(16) float g_xn [ROWS*Cq];
__device__ __align__(16) float g_r  [ROWS*Cq];
__device__ __align__(16) float g_k  [ROWS*Cq];
__device__ __align__(16) float g_v  [ROWS*Cq];
__device__ __align__(16) float g_g  [ROWS*Cq];
__device__ __align__(16) float g_y  [ROWS*Cq];
__device__ __align__(16) float g_x1 [ROWS*Cq];
__device__ __align__(16) float g_kv [ROWS*Cq];
// bf16 hi/lo activation pairs
__device__ __align__(16) __nv_bfloat16 g_xrh[ROWS*Cq], g_xrl[ROWS*Cq];
__device__ __align__(16) __nv_bfloat16 g_xkh[ROWS*Cq], g_xkl[ROWS*Cq];
__device__ __align__(16) __nv_bfloat16 g_xvh[ROWS*Cq], g_xvl[ROWS*Cq];
__device__ __align__(16) __nv_bfloat16 g_xgh[ROWS*Cq], g_xgl[ROWS*Cq];   // reused for z
__device__ __align__(16) __nv_bfloat16 g_kfh[(size_t)ROWS*FFNq], g_kfl[(size_t)ROWS*FFNq];
// bf16 hi/lo weight pairs
__device__ __align__(16) __nv_bfloat16 g_wrh[Cq*Cq],  g_wrl[Cq*Cq];
__device__ __align__(16) __nv_bfloat16 g_wkh[Cq*Cq],  g_wkl[Cq*Cq];
__device__ __align__(16) __nv_bfloat16 g_wvh[Cq*Cq],  g_wvl[Cq*Cq];
__device__ __align__(16) __nv_bfloat16 g_wgh[Cq*Cq],  g_wgl[Cq*Cq];
__device__ __align__(16) __nv_bfloat16 g_woh[Cq*Cq],  g_wol[Cq*Cq];
__device__ __align__(16) __nv_bfloat16 g_fkh[FFNq*Cq],g_fkl[FFNq*Cq];
__device__ __align__(16) __nv_bfloat16 g_frh[Cq*Cq],  g_frl[Cq*Cq];
__device__ __align__(16) __nv_bfloat16 g_fvh[Cq*FFNq],g_fvl[Cq*FFNq];

// ---------------- helpers ----------------------------------------------------
__device__ __forceinline__ uint32_t smem_u32(const void* p) {
    uint32_t a;
    asm("{ .reg .u64 t; cvta.to.shared.u64 t, %1; cvt.u32.u64 %0, t; }" : "=r"(a) : "l"(p));
    return a;
}
__device__ __forceinline__ void cp16(uint32_t dst, const void* src) {
    asm volatile("cp.async.cg.shared.global [%0], [%1], 16;" :: "r"(dst), "l"(src) : "memory");
}
__device__ __forceinline__ void cp_commit() {
    asm volatile("cp.async.commit_group;" ::: "memory");
}
template<int N>
__device__ __forceinline__ void cp_wait() {
    asm volatile("cp.async.wait_group %0;" :: "n"(N) : "memory");
}
__device__ __forceinline__ uint32_t lds32(uint32_t a) {
    uint32_t v;
    asm volatile("ld.shared.b32 %0, [%1];" : "=r"(v) : "r"(a));
    return v;
}
__device__ __forceinline__ void mma16816(float* c, const uint32_t* a, const uint32_t* b) {
    asm volatile("mma.sync.aligned.m16n8k16.row.col.f32.bf16.bf16.f32 "
        "{%0,%1,%2,%3}, {%4,%5,%6,%7}, {%8,%9}, {%0,%1,%2,%3};"
        : "+f"(c[0]), "+f"(c[1]), "+f"(c[2]), "+f"(c[3])
        : "r"(a[0]), "r"(a[1]), "r"(a[2]), "r"(a[3]), "r"(b[0]), "r"(b[1]));
}
__device__ __forceinline__ void split2(float v, __nv_bfloat16& h, __nv_bfloat16& l) {
    h = __float2bfloat16(v);
    l = __float2bfloat16(v - __bfloat162float(h));
}
__device__ __forceinline__ uint32_t pack2(__nv_bfloat16 a, __nv_bfloat16 b) {
    return (uint32_t)__bfloat16_as_ushort(a) | ((uint32_t)__bfloat16_as_ushort(b) << 16);
}

// ---------------- mma.sync split-bf16 NT GEMM -------------------------------
// out[m][n] = epi( sum_k A[m][k]*W[n][k] ),  A,W given as bf16 hi/lo pairs.
// EPI: 0 plain fp32, 1 res+acc fp32, 2 relu(acc)^2 -> bf16 hi/lo, 3 res+sigmoid(acc)*aux
// CTA 128x128, 256 thr = 2(m) x 4(n) warps, warp 64x32. K-chunk 32 bf16.
#define KC 32
#define PSTR 80                      // padded smem row stride in bytes (40 bf16)
#define MATB (128*PSTR)              // 10240 bytes per matrix tile
#define STAGEB (4*MATB)              // 40960 per stage
#define GEMM_SMEM (2*STAGEB)         // 81920

__device__ __forceinline__ void stage_load(
    uint32_t stg, const __nv_bfloat16* Ah, const __nv_bfloat16* Al,
    const __nv_bfloat16* Bh, const __nv_bfloat16* Bl,
    int bm, int bn, int K, int k0, int tid)
{
    #pragma unroll
    for (int it = 0; it < 2; it++) {
        int idx = tid * 2 + it;        // 0..511
        int row = idx >> 2, seg = idx & 3;
        uint32_t d = stg + row * PSTR + seg * 16;
        size_t ao = (size_t)(bm + row) * K + k0 + seg * 8;
        size_t bo = (size_t)(bn + row) * K + k0 + seg * 8;
        cp16(d,          Ah + ao);
        cp16(d + MATB,   Al + ao);
        cp16(d + 2*MATB, Bh + bo);
        cp16(d + 3*MATB, Bl + bo);
    }
}

template<int EPI>
__global__ void __launch_bounds__(256, 1)
gemm_tc(const __nv_bfloat16* __restrict__ Ahi, const __nv_bfloat16* __restrict__ Alo,
        const __nv_bfloat16* __restrict__ Whi, const __nv_bfloat16* __restrict__ Wlo,
        float* __restrict__ out, int N, int K,
        const float* __restrict__ res, const float* __restrict__ aux,
        __nv_bfloat16* __restrict__ out_h, __nv_bfloat16* __restrict__ out_l)
{
    extern __shared__ __align__(16) char smem[];
    const uint32_t sb = smem_u32(smem);
    const int tid = threadIdx.x;
    const int bm = blockIdx.y * 128, bn = blockIdx.x * 128;
    const int warp = tid >> 5, lane = tid & 31;
    const int wm = warp >> 2, wn = warp & 3;           // 2 x 4 warp grid
    const int r = lane >> 2, c4 = lane & 3;

    float acc[4][4][4];
    #pragma unroll
    for (int i = 0; i < 4; i++)
        #pragma unroll
        for (int j = 0; j < 4; j++)
            #pragma unroll
            for (int q = 0; q < 4; q++) acc[i][j][q] = 0.f;

    const int nchunk = K / KC;
    stage_load(sb, Ahi, Alo, Whi, Wlo, bm, bn, K, 0, tid);
    cp_commit();

    // per-warp fragment base byte offsets within a matrix tile
    const uint32_t aBase = (uint32_t)(wm*64 + r) * PSTR + c4 * 4;
    const uint32_t bBase = (uint32_t)(wn*32 + r) * PSTR + c4 * 4;

    for (int c = 0; c < nchunk; c++) {
        if (c + 1 < nchunk) {
            stage_load(sb + ((c+1)&1)*STAGEB, Ahi, Alo, Whi, Wlo, bm, bn, K, (c+1)*KC, tid);
            cp_commit();
            cp_wait<1>();
        } else {
            cp_wait<0>();
        }
        __syncthreads();
        const uint32_t st = sb + (c & 1) * STAGEB;
        #pragma unroll
        for (int ks = 0; ks < 2; ks++) {
            const uint32_t ko = ks * 32;               // 16 bf16 = 32 bytes
            uint32_t ah[4][4], al[4][4], bh[4][2], bl[4][2];
            #pragma unroll
            for (int mt = 0; mt < 4; mt++) {
                uint32_t o = st + aBase + mt*16*PSTR + ko;
                ah[mt][0] = lds32(o);
                ah[mt][1] = lds32(o + 8*PSTR);
                ah[mt][2] = lds32(o + 16);
                ah[mt][3] = lds32(o + 8*PSTR + 16);
                o += MATB;
                al[mt][0] = lds32(o);
                al[mt][1] = lds32(o + 8*PSTR);
                al[mt][2] = lds32(o + 16);
                al[mt][3] = lds32(o + 8*PSTR + 16);
            }
            #pragma unroll
            for (int nt = 0; nt < 4; nt++) {
                uint32_t o = st + 2*MATB + bBase + nt*8*PSTR + ko;
                bh[nt][0] = lds32(o);
                bh[nt][1] = lds32(o + 16);
                o += MATB;
                bl[nt][0] = lds32(o);
                bl[nt][1] = lds32(o + 16);
            }
            #pragma unroll
            for (int mt = 0; mt < 4; mt++)
                #pragma unroll
                for (int nt = 0; nt < 4; nt++) {
                    mma16816(acc[mt][nt], ah[mt], bh[nt]);
                    mma16816(acc[mt][nt], ah[mt], bl[nt]);
                    mma16816(acc[mt][nt], al[mt], bh[nt]);
                }
        }
        __syncthreads();
    }

    // epilogue: acc reg q: rows m0 (q<2) / m0+8 (q>=2), cols n0 + (q&1)
    #pragma unroll
    for (int mt = 0; mt < 4; mt++) {
        #pragma unroll
        for (int nt = 0; nt < 4; nt++) {
            const int m0 = bm + wm*64 + mt*16 + r;
            const int n0 = bn + wn*32 + nt*8 + c4*2;
            #pragma unroll
            for (int half = 0; half < 2; half++) {
                const int m_ = m0 + half*8;
                const size_t ob = (size_t)m_ * N + n0;
                float v0 = acc[mt][nt][half*2], v1 = acc[mt][nt][half*2+1];
                if (EPI == 0) {
                    *(float2*)(out + ob) = make_float2(v0, v1);
                } else if (EPI == 1) {
                    float2 rv = *(const float2*)(res + ob);
                    *(float2*)(out + ob) = make_float2(rv.x + v0, rv.y + v1);
                } else if (EPI == 3) {
                    float2 rv = *(const float2*)(res + ob);
                    float2 av = *(const float2*)(aux + ob);
                    float s0 = 1.f/(1.f + __expf(-v0));
                    float s1 = 1.f/(1.f + __expf(-v1));
                    *(float2*)(out + ob) = make_float2(rv.x + s0*av.x, rv.y + s1*av.y);
                } else { // relu^2 -> bf16 hi/lo
                    float t0 = fmaxf(v0, 0.f); t0 *= t0;
                    float t1 = fmaxf(v1, 0.f); t1 *= t1;
                    __nv_bfloat16 h0,l0,h1,l1;
                    split2(t0,h0,l0); split2(t1,h1,l1);
                    *(uint32_t*)(out_h + ob) = pack2(h0,h1);
                    *(uint32_t*)(out_l + ob) = pack2(l0,l1);
                }
            }
        }
    }
}

// ---------------- block reduce (sum pair) over 256 threads ------------------
__device__ __forceinline__ void block_reduce_2(float& a, float& b) {
    __shared__ float sa[8], sb2[8];
    int lane = threadIdx.x & 31, wid = threadIdx.x >> 5;
    #pragma unroll
    for (int o = 16; o > 0; o >>= 1) {
        a += __shfl_xor_sync(0xffffffffu, a, o);
        b += __shfl_xor_sync(0xffffffffu, b, o);
    }
    if (lane == 0) { sa[wid] = a; sb2[wid] = b; }
    __syncthreads();
    a = 0.f; b = 0.f;
    #pragma unroll
    for (int i = 0; i < 8; i++) { a += sa[i]; b += sb2[i]; }
    __syncthreads();
}

// ---------------- fused ln0 + ln1 -------------------------------------------
__global__ void ln01_kernel(const float* __restrict__ x,
                            const float* __restrict__ w0, const float* __restrict__ b0,
                            const float* __restrict__ w1, const float* __restrict__ b1,
                            float* __restrict__ x0, float* __restrict__ xn) {
    int row = blockIdx.x, tid = threadIdx.x;
    size_t off = (size_t)row * Cq;
    float v[4]; float s = 0.f, s2 = 0.f;
    #pragma unroll
    for (int i = 0; i < 4; i++) {
        v[i] = x[off + tid + i*256];
        s += v[i]; s2 += v[i]*v[i];
    }
    block_reduce_2(s, s2);
    float mu = s * (1.f/Cq);
    float inv = rsqrtf(s2*(1.f/Cq) - mu*mu + EPSq);
    float o[4]; s = 0.f; s2 = 0.f;
    #pragma unroll
    for (int i = 0; i < 4; i++) {
        int c = tid + i*256;
        o[i] = (v[i]-mu)*inv*w0[c] + b0[c];
        x0[off + c] = o[i];
        s += o[i]; s2 += o[i]*o[i];
    }
    block_reduce_2(s, s2);
    mu = s * (1.f/Cq);
    inv = rsqrtf(s2*(1.f/Cq) - mu*mu + EPSq);
    #pragma unroll
    for (int i = 0; i < 4; i++) {
        int c = tid + i*256;
        xn[off + c] = (o[i]-mu)*inv*w1[c] + b1[c];
    }
}

__global__ void ln_kernel(const float* __restrict__ x,
                          const float* __restrict__ w, const float* __restrict__ b,
                          float* __restrict__ out) {
    int row = blockIdx.x, tid = threadIdx.x;
    size_t off = (size_t)row * Cq;
    float v[4]; float s = 0.f, s2 = 0.f;
    #pragma unroll
    for (int i = 0; i < 4; i++) {
        v[i] = x[off + tid + i*256];
        s += v[i]; s2 += v[i]*v[i];
    }
    block_reduce_2(s, s2);
    float mu = s * (1.f/Cq);
    float inv = rsqrtf(s2*(1.f/Cq) - mu*mu + EPSq);
    #pragma unroll
    for (int i = 0; i < 4; i++) {
        int c = tid + i*256;
        out[off + c] = (v[i]-mu)*inv*w[c] + b[c];
    }
}

// ---------------- token-shift mixes (emit bf16 hi/lo) -----------------------
__global__ void mix4_kernel(const float* __restrict__ xn,
                            const float* __restrict__ tmk, const float* __restrict__ tmv,
                            const float* __restrict__ tmr, const float* __restrict__ tmg,
                            __nv_bfloat16* __restrict__ xkh, __nv_bfloat16* __restrict__ xkl,
                            __nv_bfloat16* __restrict__ xvh, __nv_bfloat16* __restrict__ xvl,
                            __nv_bfloat16* __restrict__ xrh, __nv_bfloat16* __restrict__ xrl,
                            __nv_bfloat16* __restrict__ xgh, __nv_bfloat16* __restrict__ xgl) {
    int row = blockIdx.x, tid = threadIdx.x;
    int t = row & (Tq-1);
    size_t off = (size_t)row * Cq;
    #pragma unroll
    for (int i = 0; i < 2; i++) {
        int c = (tid + i*256) * 2;
        float2 cur = *(const float2*)(xn + off + c);
        float2 prv = (t > 0) ? *(const float2*)(xn + off - Cq + c) : make_float2(0.f, 0.f);
        float2 mk = *(const float2*)(tmk + c), mv = *(const float2*)(tmv + c);
        float2 mr = *(const float2*)(tmr + c), mg = *(const float2*)(tmg + c);
        __nv_bfloat16 h0,l0,h1,l1;
        float a0 = cur.x*mk.x + prv.x*(1.f-mk.x), a1 = cur.y*mk.y + prv.y*(1.f-mk.y);
        split2(a0,h0,l0); split2(a1,h1,l1);
        *(uint32_t*)(xkh+off+c) = pack2(h0,h1); *(uint32_t*)(xkl+off+c) = pack2(l0,l1);
        a0 = cur.x*mv.x + prv.x*(1.f-mv.x); a1 = cur.y*mv.y + prv.y*(1.f-mv.y);
        split2(a0,h0,l0); split2(a1,h1,l1);
        *(uint32_t*)(xvh+off+c) = pack2(h0,h1); *(uint32_t*)(xvl+off+c) = pack2(l0,l1);
        a0 = cur.x*mr.x + prv.x*(1.f-mr.x); a1 = cur.y*mr.y + prv.y*(1.f-mr.y);
        split2(a0,h0,l0); split2(a1,h1,l1);
        *(uint32_t*)(xrh+off+c) = pack2(h0,h1); *(uint32_t*)(xrl+off+c) = pack2(l0,l1);
        a0 = cur.x*mg.x + prv.x*(1.f-mg.x); a1 = cur.y*mg.y + prv.y*(1.f-mg.y);
        split2(a0,h0,l0); split2(a1,h1,l1);
        *(uint32_t*)(xgh+off+c) = pack2(h0,h1); *(uint32_t*)(xgl+off+c) = pack2(l0,l1);
    }
}

__global__ void mix2_kernel(const float* __restrict__ xn,
                            const float* __restrict__ tmk, const float* __restrict__ tmr,
                            __nv_bfloat16* __restrict__ xkh, __nv_bfloat16* __restrict__ xkl,
                            __nv_bfloat16* __restrict__ xrh, __nv_bfloat16* __restrict__ xrl) {
    int row = blockIdx.x, tid = threadIdx.x;
    int t = row & (Tq-1);
    size_t off = (size_t)row * Cq;
    #pragma unroll
    for (int i = 0; i < 2; i++) {
        int c = (tid + i*256) * 2;
        float2 cur = *(const float2*)(xn + off + c);
        float2 prv = (t > 0) ? *(const float2*)(xn + off - Cq + c) : make_float2(0.f, 0.f);
        float2 mk = *(const float2*)(tmk + c), mr = *(const float2*)(tmr + c);
        __nv_bfloat16 h0,l0,h1,l1;
        float a0 = cur.x*mk.x + prv.x*(1.f-mk.x), a1 = cur.y*mk.y + prv.y*(1.f-mk.y);
        split2(a0,h0,l0); split2(a1,h1,l1);
        *(uint32_t*)(xkh+off+c) = pack2(h0,h1); *(uint32_t*)(xkl+off+c) = pack2(l0,l1);
        a0 = cur.x*mr.x + prv.x*(1.f-mr.x); a1 = cur.y*mr.y + prv.y*(1.f-mr.y);
        split2(a0,h0,l0); split2(a1,h1,l1);
        *(uint32_t*)(xrh+off+c) = pack2(h0,h1); *(uint32_t*)(xrl+off+c) = pack2(l0,l1);
    }
}

// ---------------- weight fp32 -> bf16 hi/lo ----------------------------------
__global__ void cvt_kernel(const float* __restrict__ in,
                           __nv_bfloat16* __restrict__ h, __nv_bfloat16* __restrict__ l,
                           int n4) {
    int i = blockIdx.x * 256 + threadIdx.x;
    if (i >= n4) return;
    float4 v = ((const float4*)in)[i];
    __nv_bfloat16 h0,l0,h1,l1,h2,l2,h3,l3;
    split2(v.x,h0,l0); split2(v.y,h1,l1); split2(v.z,h2,l2); split2(v.w,h3,l3);
    ((uint2*)h)[i] = make_uint2(pack2(h0,h1), pack2(h2,h3));
    ((uint2*)l)[i] = make_uint2(pack2(l0,l1), pack2(l2,l3));
}

// ---------------- wkv5 recurrence -------------------------------------------
__global__ void __launch_bounds__(256)
wkv5_kernel(const float* __restrict__ r, const float* __restrict__ k,
            const float* __restrict__ v, const float* __restrict__ w,
            const float* __restrict__ u, float* __restrict__ y) {
    int bh = blockIdx.x;
    int b = bh >> 4, h = bh & 15;
    int tid = threadIdx.x;
    int j = tid >> 2, q = tid & 3, i0 = q * 16;

    __shared__ float rs[64], ks[64], vs[64], us[64], csh;
    if (tid < 64) us[tid] = u[h*64 + tid];

    float s[16], ew[16];
    #pragma unroll
    for (int ii = 0; ii < 16; ii++) {
        s[ii] = 0.f;
        ew[ii] = expf(-expf(w[h*64 + i0 + ii]));
    }
    __syncthreads();

    size_t base = (size_t)b * Tq * Cq + h * 64;
    for (int t = 0; t < Tq; t++) {
        size_t off = base + (size_t)t * Cq;
        if (tid < 64)       rs[tid]      = r[off + tid];
        else if (tid < 128) ks[tid-64]   = k[off + tid - 64];
        else if (tid < 192) vs[tid-128]  = v[off + tid - 128];
        __syncthreads();
        if (tid < 32) {
            float p = rs[tid]*us[tid]*ks[tid] + rs[tid+32]*us[tid+32]*ks[tid+32];
            #pragma unroll
            for (int o = 16; o > 0; o >>= 1) p += __shfl_xor_sync(0xffffffffu, p, o);
            if (tid == 0) csh = p;
        }
        __syncthreads();
        float vj = vs[j];
        float yp = 0.f;
        #pragma unroll
        for (int ii = 0; ii < 16; ii++) {
            yp = fmaf(rs[i0+ii], s[ii], yp);
            s[ii] = fmaf(ew[ii], s[ii], ks[i0+ii]*vj);
        }
        yp += __shfl_xor_sync(0xffffffffu, yp, 1);
        yp += __shfl_xor_sync(0xffffffffu, yp, 2);
        if (q == 0) y[off + j] = yp + csh * vj;
        __syncthreads();
    }
}

// ---------------- groupnorm(y/8)*silu(g) -> z hi/lo bf16 --------------------
__global__ void gngate_kernel(const float* __restrict__ y, const float* __restrict__ g,
                              const float* __restrict__ w, const float* __restrict__ b,
                              __nv_bfloat16* __restrict__ zh, __nv_bfloat16* __restrict__ zl) {
    int idx = blockIdx.x;              // row*H + h
    int h = idx & (Hq-1);
    size_t off = (size_t)(idx >> 4) * Cq + h * 64;
    int lane = threadIdx.x;
    float y0 = y[off + lane]      * 0.125f;
    float y1 = y[off + lane + 32] * 0.125f;
    float s = y0 + y1, s2 = y0*y0 + y1*y1;
    #pragma unroll
    for (int o = 16; o > 0; o >>= 1) {
        s  += __shfl_xor_sync(0xffffffffu, s, o);
        s2 += __shfl_xor_sync(0xffffffffu, s2, o);
    }
    float mu = s * (1.f/64.f);
    float inv = rsqrtf(s2*(1.f/64.f) - mu*mu + EPSq);
    int c0 = h*64 + lane;
    float g0 = g[off + lane];
    float g1 = g[off + lane + 32];
    float si0 = g0 / (1.f + __expf(-g0));
    float si1 = g1 / (1.f + __expf(-g1));
    float z0 = ((y0-mu)*inv*w[c0]    + b[c0])    * si0;
    float z1 = ((y1-mu)*inv*w[c0+32] + b[c0+32]) * si1;
    __nv_bfloat16 h0,l0,h1,l1;
    split2(z0,h0,l0); split2(z1,h1,l1);
    zh[off + lane]      = h0;  zl[off + lane]      = l0;
    zh[off + lane + 32] = h1;  zl[off + lane + 32] = l1;
}

// ---------------- launch ----------------------------------------------------
extern "C" void kernel_launch(void* const* d_in, const int* in_sizes, int n_in,
                              void* d_out, int out_size) {
    const float* x        = (const float*)d_in[0];
    const float* ln0_w    = (const float*)d_in[1];
    const float* ln0_b    = (const float*)d_in[2];
    const float* ln1_w    = (const float*)d_in[3];
    const float* ln1_b    = (const float*)d_in[4];
    const float* ln2_w    = (const float*)d_in[5];
    const float* ln2_b    = (const float*)d_in[6];
    const float* att_tmk  = (const float*)d_in[7];
    const float* att_tmv  = (const float*)d_in[8];
    const float* att_tmr  = (const float*)d_in[9];
    const float* att_tmg  = (const float*)d_in[10];
    const float* att_decay= (const float*)d_in[11];
    const float* att_faaaa= (const float*)d_in[12];
    const float* att_Wr   = (const float*)d_in[13];
    const float* att_Wk   = (const float*)d_in[14];
    const float* att_Wv   = (const float*)d_in[15];
    const float* att_Wg   = (const float*)d_in[16];
    const float* att_Wo   = (const float*)d_in[17];
    const float* lnx_w    = (const float*)d_in[18];
    const float* lnx_b    = (const float*)d_in[19];
    const float* ffn_tmk  = (const float*)d_in[20];
    const float* ffn_tmr  = (const float*)d_in[21];
    const float* ffn_Wk   = (const float*)d_in[22];
    const float* ffn_Wr   = (const float*)d_in[23];
    const float* ffn_Wv   = (const float*)d_in[24];
    float* out = (float*)d_out;

    float *x0,*xn,*r_,*k_,*v_,*g_,*y_,*x1,*kv;
    cudaGetSymbolAddress((void**)&x0, g_x0);
    cudaGetSymbolAddress((void**)&xn, g_xn);
    cudaGetSymbolAddress((void**)&r_, g_r);
    cudaGetSymbolAddress((void**)&k_, g_k);
    cudaGetSymbolAddress((void**)&v_, g_v);
    cudaGetSymbolAddress((void**)&g_, g_g);
    cudaGetSymbolAddress((void**)&y_, g_y);
    cudaGetSymbolAddress((void**)&x1, g_x1);
    cudaGetSymbolAddress((void**)&kv, g_kv);

    __nv_bfloat16 *xrh,*xrl,*xkh,*xkl,*xvh,*xvl,*xgh,*xgl,*kfh,*kfl;
    __nv_bfloat16 *wrh,*wrl,*wkh,*wkl,*wvh,*wvl,*wgh,*wgl,*woh,*wol,*fkh,*fkl,*frh,*frl,*fvh,*fvl;
    cudaGetSymbolAddress((void**)&xrh, g_xrh); cudaGetSymbolAddress((void**)&xrl, g_xrl);
    cudaGetSymbolAddress((void**)&xkh, g_xkh); cudaGetSymbolAddress((void**)&xkl, g_xkl);
    cudaGetSymbolAddress((void**)&xvh, g_xvh); cudaGetSymbolAddress((void**)&xvl, g_xvl);
    cudaGetSymbolAddress((void**)&xgh, g_xgh); cudaGetSymbolAddress((void**)&xgl, g_xgl);
    cudaGetSymbolAddress((void**)&kfh, g_kfh); cudaGetSymbolAddress((void**)&kfl, g_kfl);
    cudaGetSymbolAddress((void**)&wrh, g_wrh); cudaGetSymbolAddress((void**)&wrl, g_wrl);
    cudaGetSymbolAddress((void**)&wkh, g_wkh); cudaGetSymbolAddress((void**)&wkl, g_wkl);
    cudaGetSymbolAddress((void**)&wvh, g_wvh); cudaGetSymbolAddress((void**)&wvl, g_wvl);
    cudaGetSymbolAddress((void**)&wgh, g_wgh); cudaGetSymbolAddress((void**)&wgl, g_wgl);
    cudaGetSymbolAddress((void**)&woh, g_woh); cudaGetSymbolAddress((void**)&wol, g_wol);
    cudaGetSymbolAddress((void**)&fkh, g_fkh); cudaGetSymbolAddress((void**)&fkl, g_fkl);
    cudaGetSymbolAddress((void**)&frh, g_frh); cudaGetSymbolAddress((void**)&frl, g_frl);
    cudaGetSymbolAddress((void**)&fvh, g_fvh); cudaGetSymbolAddress((void**)&fvl, g_fvl);

    cudaFuncSetAttribute(gemm_tc<0>, cudaFuncAttributeMaxDynamicSharedMemorySize, GEMM_SMEM);
    cudaFuncSetAttribute(gemm_tc<1>, cudaFuncAttributeMaxDynamicSharedMemorySize, GEMM_SMEM);
    cudaFuncSetAttribute(gemm_tc<2>, cudaFuncAttributeMaxDynamicSharedMemorySize, GEMM_SMEM);
    cudaFuncSetAttribute(gemm_tc<3>, cudaFuncAttributeMaxDynamicSharedMemorySize, GEMM_SMEM);

    dim3 blk256(256);
    const int nCC = Cq*Cq/4, nFC = FFNq*Cq/4;
    // weight splits
    cvt_kernel<<<nCC/256, 256>>>(att_Wr, wrh, wrl, nCC);
    cvt_kernel<<<nCC/256, 256>>>(att_Wk, wkh, wkl, nCC);
    cvt_kernel<<<nCC/256, 256>>>(att_Wv, wvh, wvl, nCC);
    cvt_kernel<<<nCC/256, 256>>>(att_Wg, wgh, wgl, nCC);
    cvt_kernel<<<nCC/256, 256>>>(att_Wo, woh, wol, nCC);
    cvt_kernel<<<nFC/256, 256>>>(ffn_Wk, fkh, fkl, nFC);
    cvt_kernel<<<nCC/256, 256>>>(ffn_Wr, frh, frl, nCC);
    cvt_kernel<<<nFC/256, 256>>>(ffn_Wv, fvh, fvl, nFC);

    dim3 gCC(Cq/128, ROWS/128);       // (8, 128)
    dim3 gCF(FFNq/128, ROWS/128);     // (28, 128)

    // 1) ln0 + ln1
    ln01_kernel<<<ROWS, blk256>>>(x, ln0_w, ln0_b, ln1_w, ln1_b, x0, xn);
    // 2) token-shift mixes (attention) -> bf16 hi/lo
    mix4_kernel<<<ROWS, blk256>>>(xn, att_tmk, att_tmv, att_tmr, att_tmg,
                                  xkh, xkl, xvh, xvl, xrh, xrl, xgh, xgl);
    // 3) projections (mma.sync split-bf16)
    gemm_tc<0><<<gCC, 256, GEMM_SMEM>>>(xrh, xrl, wrh, wrl, r_, Cq, Cq, nullptr, nullptr, nullptr, nullptr);
    gemm_tc<0><<<gCC, 256, GEMM_SMEM>>>(xkh, xkl, wkh, wkl, k_, Cq, Cq, nullptr, nullptr, nullptr, nullptr);
    gemm_tc<0><<<gCC, 256, GEMM_SMEM>>>(xvh, xvl, wvh, wvl, v_, Cq, Cq, nullptr, nullptr, nullptr, nullptr);
    gemm_tc<0><<<gCC, 256, GEMM_SMEM>>>(xgh, xgl, wgh, wgl, g_, Cq, Cq, nullptr, nullptr, nullptr, nullptr);
    // 4) wkv5 recurrence
    wkv5_kernel<<<Bq*Hq, blk256>>>(r_, k_, v_, att_decay, att_faaaa, y_);
    // 5) groupnorm + gate -> z hi/lo (reuse xg buffers)
    gngate_kernel<<<ROWS*Hq, 32>>>(y_, g_, lnx_w, lnx_b, xgh, xgl);
    // 6) output projection + residual
    gemm_tc<1><<<gCC, 256, GEMM_SMEM>>>(xgh, xgl, woh, wol, x1, Cq, Cq, x0, nullptr, nullptr, nullptr);
    // 7) channel-mix
    ln_kernel<<<ROWS, blk256>>>(x1, ln2_w, ln2_b, xn);
    mix2_kernel<<<ROWS, blk256>>>(xn, ffn_tmk, ffn_tmr, xkh, xkl, xrh, xrl);
    gemm_tc<2><<<gCF, 256, GEMM_SMEM>>>(xkh, xkl, fkh, fkl, nullptr, FFNq, Cq, nullptr, nullptr, kfh, kfl);
    gemm_tc<0><<<gCC, 256, GEMM_SMEM>>>(kfh, kfl, fvh, fvl, kv, Cq, FFNq, nullptr, nullptr, nullptr, nullptr);
    gemm_tc<3><<<gCC, 256, GEMM_SMEM>>>(xrh, xrl, frh, frl, out, Cq, Cq, x1, kv, nullptr, nullptr);
}

// round 10
// speedup vs baseline: 2.3391x; 1.1126x over previous
#include <cuda_runtime.h>
#include <cuda_bf16.h>
#include <cstdint>
#include <math.h>

#define Bq 8
#define Tq 2048
#define Cq 1024
#define Hq 16
#define Nq 64
#define FFNq 3584
#define EPSq 1e-5f
#define ROWS (Bq*Tq)            // 16384

// ---------------- scratch (device globals; no cudaMalloc allowed) -----------
__device__ __align__(16) float g_x0 [ROWS*Cq];
__device__ __align__(16) float g_xn [ROWS*Cq];
__device__ __align__(16) float g_r  [ROWS*Cq];
__device__ __align__(16) float g_k  [ROWS*Cq];
__device__ __align__(16) float g_v  [ROWS*Cq];
__device__ __align__(16) float g_g  [ROWS*Cq];
__device__ __align__(16) float g_y  [ROWS*Cq];
__device__ __align__(16) float g_x1 [ROWS*Cq];
__device__ __align__(16) float g_kv [ROWS*Cq];
// bf16 hi/lo activation pairs
__device__ __align__(16) __nv_bfloat16 g_xrh[ROWS*Cq], g_xrl[ROWS*Cq];
__device__ __align__(16) __nv_bfloat16 g_xkh[ROWS*Cq], g_xkl[ROWS*Cq];
__device__ __align__(16) __nv_bfloat16 g_xvh[ROWS*Cq], g_xvl[ROWS*Cq];
__device__ __align__(16) __nv_bfloat16 g_xgh[ROWS*Cq], g_xgl[ROWS*Cq];   // reused for z
__device__ __align__(16) __nv_bfloat16 g_kfh[(size_t)ROWS*FFNq], g_kfl[(size_t)ROWS*FFNq];
// bf16 hi/lo weight pairs
__device__ __align__(16) __nv_bfloat16 g_wrh[Cq*Cq],  g_wrl[Cq*Cq];
__device__ __align__(16) __nv_bfloat16 g_wkh[Cq*Cq],  g_wkl[Cq*Cq];
__device__ __align__(16) __nv_bfloat16 g_wvh[Cq*Cq],  g_wvl[Cq*Cq];
__device__ __align__(16) __nv_bfloat16 g_wgh[Cq*Cq],  g_wgl[Cq*Cq];
__device__ __align__(16) __nv_bfloat16 g_woh[Cq*Cq],  g_wol[Cq*Cq];
__device__ __align__(16) __nv_bfloat16 g_fkh[FFNq*Cq],g_fkl[FFNq*Cq];
__device__ __align__(16) __nv_bfloat16 g_frh[Cq*Cq],  g_frl[Cq*Cq];
__device__ __align__(16) __nv_bfloat16 g_fvh[Cq*FFNq],g_fvl[Cq*FFNq];

// ---------------- helpers ----------------------------------------------------
__device__ __forceinline__ uint32_t smem_u32(const void* p) {
    uint32_t a;
    asm("{ .reg .u64 t; cvta.to.shared.u64 t, %1; cvt.u32.u64 %0, t; }" : "=r"(a) : "l"(p));
    return a;
}
__device__ __forceinline__ void cp16(uint32_t dst, const void* src) {
    asm volatile("cp.async.cg.shared.global [%0], [%1], 16;" :: "r"(dst), "l"(src) : "memory");
}
__device__ __forceinline__ void cp_commit() {
    asm volatile("cp.async.commit_group;" ::: "memory");
}
template<int N>
__device__ __forceinline__ void cp_wait() {
    asm volatile("cp.async.wait_group %0;" :: "n"(N) : "memory");
}
__device__ __forceinline__ void ldm4(uint32_t* r, uint32_t addr) {
    asm volatile("ldmatrix.sync.aligned.m8n8.x4.shared.b16 {%0,%1,%2,%3}, [%4];"
        : "=r"(r[0]), "=r"(r[1]), "=r"(r[2]), "=r"(r[3]) : "r"(addr));
}
__device__ __forceinline__ void mma16816(float* c, const uint32_t* a, const uint32_t* b) {
    asm volatile("mma.sync.aligned.m16n8k16.row.col.f32.bf16.bf16.f32 "
        "{%0,%1,%2,%3}, {%4,%5,%6,%7}, {%8,%9}, {%0,%1,%2,%3};"
        : "+f"(c[0]), "+f"(c[1]), "+f"(c[2]), "+f"(c[3])
        : "r"(a[0]), "r"(a[1]), "r"(a[2]), "r"(a[3]), "r"(b[0]), "r"(b[1]));
}
__device__ __forceinline__ void split2(float v, __nv_bfloat16& h, __nv_bfloat16& l) {
    h = __float2bfloat16(v);
    l = __float2bfloat16(v - __bfloat162float(h));
}
__device__ __forceinline__ uint32_t pack2(__nv_bfloat16 a, __nv_bfloat16 b) {
    return (uint32_t)__bfloat16_as_ushort(a) | ((uint32_t)__bfloat16_as_ushort(b) << 16);
}

// ---------------- mma.sync split-bf16 NT GEMM -------------------------------
// out[m][n] = epi( sum_k A[m][k]*W[n][k] ),  A,W given as bf16 hi/lo pairs.
// EPI: 0 plain fp32, 1 res+acc fp32, 2 relu(acc)^2 -> bf16 hi/lo, 3 res+sigmoid(acc)*aux
// CTA 128x128, 256 thr = 2(m) x 4(n) warps, warp 64x32. K-chunk 32 bf16.
#define KC 32
#define PSTR 80                      // padded smem row stride in bytes (40 bf16)
#define MATB (128*PSTR)              // 10240 bytes per matrix tile
#define STAGEB (4*MATB)              // 40960 per stage
#define GEMM_SMEM (2*STAGEB)         // 81920

__device__ __forceinline__ void stage_load(
    uint32_t stg, const __nv_bfloat16* Ah, const __nv_bfloat16* Al,
    const __nv_bfloat16* Bh, const __nv_bfloat16* Bl,
    int bm, int bn, int K, int k0, int tid)
{
    #pragma unroll
    for (int it = 0; it < 2; it++) {
        int idx = tid * 2 + it;        // 0..511
        int row = idx >> 2, seg = idx & 3;
        uint32_t d = stg + row * PSTR + seg * 16;
        size_t ao = (size_t)(bm + row) * K + k0 + seg * 8;
        size_t bo = (size_t)(bn + row) * K + k0 + seg * 8;
        cp16(d,          Ah + ao);
        cp16(d + MATB,   Al + ao);
        cp16(d + 2*MATB, Bh + bo);
        cp16(d + 3*MATB, Bl + bo);
    }
}

template<int EPI>
__global__ void __launch_bounds__(256, 2)
gemm_tc(const __nv_bfloat16* __restrict__ Ahi, const __nv_bfloat16* __restrict__ Alo,
        const __nv_bfloat16* __restrict__ Whi, const __nv_bfloat16* __restrict__ Wlo,
        float* __restrict__ out, int N, int K,
        const float* __restrict__ res, const float* __restrict__ aux,
        __nv_bfloat16* __restrict__ out_h, __nv_bfloat16* __restrict__ out_l)
{
    extern __shared__ __align__(16) char smem[];
    const uint32_t sb = smem_u32(smem);
    const int tid = threadIdx.x;
    const int bm = blockIdx.y * 128, bn = blockIdx.x * 128;
    const int warp = tid >> 5, lane = tid & 31;
    const int wm = warp >> 2, wn = warp & 3;           // 2 x 4 warp grid
    const int r = lane >> 2, c4 = lane & 3;

    float acc[4][4][4];
    #pragma unroll
    for (int i = 0; i < 4; i++)
        #pragma unroll
        for (int j = 0; j < 4; j++)
            #pragma unroll
            for (int q = 0; q < 4; q++) acc[i][j][q] = 0.f;

    const int nchunk = K / KC;
    stage_load(sb, Ahi, Alo, Whi, Wlo, bm, bn, K, 0, tid);
    cp_commit();

    // ldmatrix lane-address offsets (bytes within a matrix tile)
    // A (x4): sel = lane>>3: matrices (r0-7,k0-7),(r8-15,k0-7),(r0-7,k8-15),(r8-15,k8-15)
    const int aRow = wm*64 + (lane & 7) + ((lane >> 3) & 1) * 8;
    const uint32_t aOff = (uint32_t)aRow * PSTR + (lane >> 4) * 16;
    // B (x4): matrices (n0-7,k0-7),(n0-7,k8-15),(n8-15,k0-7),(n8-15,k8-15)
    const int bRow = wn*32 + (lane & 7) + (lane >> 4) * 8;
    const uint32_t bOff = (uint32_t)bRow * PSTR + ((lane >> 3) & 1) * 16;

    for (int c = 0; c < nchunk; c++) {
        if (c + 1 < nchunk) {
            stage_load(sb + ((c+1)&1)*STAGEB, Ahi, Alo, Whi, Wlo, bm, bn, K, (c+1)*KC, tid);
            cp_commit();
            cp_wait<1>();
        } else {
            cp_wait<0>();
        }
        __syncthreads();
        const uint32_t st = sb + (c & 1) * STAGEB;
        #pragma unroll
        for (int ks = 0; ks < 2; ks++) {
            const uint32_t ko = ks * 32;               // 16 bf16 = 32 bytes
            uint32_t bh[4][2], bl[4][2];
            #pragma unroll
            for (int ntp = 0; ntp < 2; ntp++) {
                uint32_t t[4];
                ldm4(t, st + 2*MATB + bOff + ntp*16*PSTR + ko);
                bh[2*ntp][0] = t[0]; bh[2*ntp][1] = t[1];
                bh[2*ntp+1][0] = t[2]; bh[2*ntp+1][1] = t[3];
                ldm4(t, st + 3*MATB + bOff + ntp*16*PSTR + ko);
                bl[2*ntp][0] = t[0]; bl[2*ntp][1] = t[1];
                bl[2*ntp+1][0] = t[2]; bl[2*ntp+1][1] = t[3];
            }
            #pragma unroll
            for (int mt = 0; mt < 4; mt++) {
                uint32_t ah[4], al[4];
                ldm4(ah, st + aOff + mt*16*PSTR + ko);
                ldm4(al, st + MATB + aOff + mt*16*PSTR + ko);
                #pragma unroll
                for (int nt = 0; nt < 4; nt++) {
                    mma16816(acc[mt][nt], ah, bh[nt]);
                    mma16816(acc[mt][nt], ah, bl[nt]);
                    mma16816(acc[mt][nt], al, bh[nt]);
                }
            }
        }
        __syncthreads();
    }

    // epilogue: acc reg q: rows m0 (q<2) / m0+8 (q>=2), cols n0 + (q&1)
    #pragma unroll
    for (int mt = 0; mt < 4; mt++) {
        #pragma unroll
        for (int nt = 0; nt < 4; nt++) {
            const int m0 = bm + wm*64 + mt*16 + r;
            const int n0 = bn + wn*32 + nt*8 + c4*2;
            #pragma unroll
            for (int half = 0; half < 2; half++) {
                const int m_ = m0 + half*8;
                const size_t ob = (size_t)m_ * N + n0;
                float v0 = acc[mt][nt][half*2], v1 = acc[mt][nt][half*2+1];
                if (EPI == 0) {
                    *(float2*)(out + ob) = make_float2(v0, v1);
                } else if (EPI == 1) {
                    float2 rv = *(const float2*)(res + ob);
                    *(float2*)(out + ob) = make_float2(rv.x + v0, rv.y + v1);
                } else if (EPI == 3) {
                    float2 rv = *(const float2*)(res + ob);
                    float2 av = *(const float2*)(aux + ob);
                    float s0 = 1.f/(1.f + __expf(-v0));
                    float s1 = 1.f/(1.f + __expf(-v1));
                    *(float2*)(out + ob) = make_float2(rv.x + s0*av.x, rv.y + s1*av.y);
                } else { // relu^2 -> bf16 hi/lo
                    float t0 = fmaxf(v0, 0.f); t0 *= t0;
                    float t1 = fmaxf(v1, 0.f); t1 *= t1;
                    __nv_bfloat16 h0,l0,h1,l1;
                    split2(t0,h0,l0); split2(t1,h1,l1);
                    *(uint32_t*)(out_h + ob) = pack2(h0,h1);
                    *(uint32_t*)(out_l + ob) = pack2(l0,l1);
                }
            }
        }
    }
}

// ---------------- block reduce (sum pair) over 256 threads ------------------
__device__ __forceinline__ void block_reduce_2(float& a, float& b) {
    __shared__ float sa[8], sb2[8];
    int lane = threadIdx.x & 31, wid = threadIdx.x >> 5;
    #pragma unroll
    for (int o = 16; o > 0; o >>= 1) {
        a += __shfl_xor_sync(0xffffffffu, a, o);
        b += __shfl_xor_sync(0xffffffffu, b, o);
    }
    if (lane == 0) { sa[wid] = a; sb2[wid] = b; }
    __syncthreads();
    a = 0.f; b = 0.f;
    #pragma unroll
    for (int i = 0; i < 8; i++) { a += sa[i]; b += sb2[i]; }
    __syncthreads();
}

// ---------------- fused ln0 + ln1 -------------------------------------------
__global__ void ln01_kernel(const float* __restrict__ x,
                            const float* __restrict__ w0, const float* __restrict__ b0,
                            const float* __restrict__ w1, const float* __restrict__ b1,
                            float* __restrict__ x0, float* __restrict__ xn) {
    int row = blockIdx.x, tid = threadIdx.x;
    size_t off = (size_t)row * Cq;
    float v[4]; float s = 0.f, s2 = 0.f;
    #pragma unroll
    for (int i = 0; i < 4; i++) {
        v[i] = x[off + tid + i*256];
        s += v[i]; s2 += v[i]*v[i];
    }
    block_reduce_2(s, s2);
    float mu = s * (1.f/Cq);
    float inv = rsqrtf(s2*(1.f/Cq) - mu*mu + EPSq);
    float o[4]; s = 0.f; s2 = 0.f;
    #pragma unroll
    for (int i = 0; i < 4; i++) {
        int c = tid + i*256;
        o[i] = (v[i]-mu)*inv*w0[c] + b0[c];
        x0[off + c] = o[i];
        s += o[i]; s2 += o[i]*o[i];
    }
    block_reduce_2(s, s2);
    mu = s * (1.f/Cq);
    inv = rsqrtf(s2*(1.f/Cq) - mu*mu + EPSq);
    #pragma unroll
    for (int i = 0; i < 4; i++) {
        int c = tid + i*256;
        xn[off + c] = (o[i]-mu)*inv*w1[c] + b1[c];
    }
}

__global__ void ln_kernel(const float* __restrict__ x,
                          const float* __restrict__ w, const float* __restrict__ b,
                          float* __restrict__ out) {
    int row = blockIdx.x, tid = threadIdx.x;
    size_t off = (size_t)row * Cq;
    float v[4]; float s = 0.f, s2 = 0.f;
    #pragma unroll
    for (int i = 0; i < 4; i++) {
        v[i] = x[off + tid + i*256];
        s += v[i]; s2 += v[i]*v[i];
    }
    block_reduce_2(s, s2);
    float mu = s * (1.f/Cq);
    float inv = rsqrtf(s2*(1.f/Cq) - mu*mu + EPSq);
    #pragma unroll
    for (int i = 0; i < 4; i++) {
        int c = tid + i*256;
        out[off + c] = (v[i]-mu)*inv*w[c] + b[c];
    }
}

// ---------------- token-shift mixes (emit bf16 hi/lo) -----------------------
__global__ void mix4_kernel(const float* __restrict__ xn,
                            const float* __restrict__ tmk, const float* __restrict__ tmv,
                            const float* __restrict__ tmr, const float* __restrict__ tmg,
                            __nv_bfloat16* __restrict__ xkh, __nv_bfloat16* __restrict__ xkl,
                            __nv_bfloat16* __restrict__ xvh, __nv_bfloat16* __restrict__ xvl,
                            __nv_bfloat16* __restrict__ xrh, __nv_bfloat16* __restrict__ xrl,
                            __nv_bfloat16* __restrict__ xgh, __nv_bfloat16* __restrict__ xgl) {
    int row = blockIdx.x, tid = threadIdx.x;
    int t = row & (Tq-1);
    size_t off = (size_t)row * Cq;
    #pragma unroll
    for (int i = 0; i < 2; i++) {
        int c = (tid + i*256) * 2;
        float2 cur = *(const float2*)(xn + off + c);
        float2 prv = (t > 0) ? *(const float2*)(xn + off - Cq + c) : make_float2(0.f, 0.f);
        float2 mk = *(const float2*)(tmk + c), mv = *(const float2*)(tmv + c);
        float2 mr = *(const float2*)(tmr + c), mg = *(const float2*)(tmg + c);
        __nv_bfloat16 h0,l0,h1,l1;
        float a0 = cur.x*mk.x + prv.x*(1.f-mk.x), a1 = cur.y*mk.y + prv.y*(1.f-mk.y);
        split2(a0,h0,l0); split2(a1,h1,l1);
        *(uint32_t*)(xkh+off+c) = pack2(h0,h1); *(uint32_t*)(xkl+off+c) = pack2(l0,l1);
        a0 = cur.x*mv.x + prv.x*(1.f-mv.x); a1 = cur.y*mv.y + prv.y*(1.f-mv.y);
        split2(a0,h0,l0); split2(a1,h1,l1);
        *(uint32_t*)(xvh+off+c) = pack2(h0,h1); *(uint32_t*)(xvl+off+c) = pack2(l0,l1);
        a0 = cur.x*mr.x + prv.x*(1.f-mr.x); a1 = cur.y*mr.y + prv.y*(1.f-mr.y);
        split2(a0,h0,l0); split2(a1,h1,l1);
        *(uint32_t*)(xrh+off+c) = pack2(h0,h1); *(uint32_t*)(xrl+off+c) = pack2(l0,l1);
        a0 = cur.x*mg.x + prv.x*(1.f-mg.x); a1 = cur.y*mg.y + prv.y*(1.f-mg.y);
        split2(a0,h0,l0); split2(a1,h1,l1);
        *(uint32_t*)(xgh+off+c) = pack2(h0,h1); *(uint32_t*)(xgl+off+c) = pack2(l0,l1);
    }
}

__global__ void mix2_kernel(const float* __restrict__ xn,
                            const float* __restrict__ tmk, const float* __restrict__ tmr,
                            __nv_bfloat16* __restrict__ xkh, __nv_bfloat16* __restrict__ xkl,
                            __nv_bfloat16* __restrict__ xrh, __nv_bfloat16* __restrict__ xrl) {
    int row = blockIdx.x, tid = threadIdx.x;
    int t = row & (Tq-1);
    size_t off = (size_t)row * Cq;
    #pragma unroll
    for (int i = 0; i < 2; i++) {
        int c = (tid + i*256) * 2;
        float2 cur = *(const float2*)(xn + off + c);
        float2 prv = (t > 0) ? *(const float2*)(xn + off - Cq + c) : make_float2(0.f, 0.f);
        float2 mk = *(const float2*)(tmk + c), mr = *(const float2*)(tmr + c);
        __nv_bfloat16 h0,l0,h1,l1;
        float a0 = cur.x*mk.x + prv.x*(1.f-mk.x), a1 = cur.y*mk.y + prv.y*(1.f-mk.y);
        split2(a0,h0,l0); split2(a1,h1,l1);
        *(uint32_t*)(xkh+off+c) = pack2(h0,h1); *(uint32_t*)(xkl+off+c) = pack2(l0,l1);
        a0 = cur.x*mr.x + prv.x*(1.f-mr.x); a1 = cur.y*mr.y + prv.y*(1.f-mr.y);
        split2(a0,h0,l0); split2(a1,h1,l1);
        *(uint32_t*)(xrh+off+c) = pack2(h0,h1); *(uint32_t*)(xrl+off+c) = pack2(l0,l1);
    }
}

// ---------------- weight fp32 -> bf16 hi/lo ----------------------------------
__global__ void cvt_kernel(const float* __restrict__ in,
                           __nv_bfloat16* __restrict__ h, __nv_bfloat16* __restrict__ l,
                           int n4) {
    int i = blockIdx.x * 256 + threadIdx.x;
    if (i >= n4) return;
    float4 v = ((const float4*)in)[i];
    __nv_bfloat16 h0,l0,h1,l1,h2,l2,h3,l3;
    split2(v.x,h0,l0); split2(v.y,h1,l1); split2(v.z,h2,l2); split2(v.w,h3,l3);
    ((uint2*)h)[i] = make_uint2(pack2(h0,h1), pack2(h2,h3));
    ((uint2*)l)[i] = make_uint2(pack2(l0,l1), pack2(l2,l3));
}

// ---------------- wkv5 recurrence -------------------------------------------
__global__ void __launch_bounds__(256)
wkv5_kernel(const float* __restrict__ r, const float* __restrict__ k,
            const float* __restrict__ v, const float* __restrict__ w,
            const float* __restrict__ u, float* __restrict__ y) {
    int bh = blockIdx.x;
    int b = bh >> 4, h = bh & 15;
    int tid = threadIdx.x;
    int j = tid >> 2, q = tid & 3, i0 = q * 16;

    __shared__ float rs[64], ks[64], vs[64], us[64], csh;
    if (tid < 64) us[tid] = u[h*64 + tid];

    float s[16], ew[16];
    #pragma unroll
    for (int ii = 0; ii < 16; ii++) {
        s[ii] = 0.f;
        ew[ii] = expf(-expf(w[h*64 + i0 + ii]));
    }
    __syncthreads();

    size_t base = (size_t)b * Tq * Cq + h * 64;
    for (int t = 0; t < Tq; t++) {
        size_t off = base + (size_t)t * Cq;
        if (tid < 64)       rs[tid]      = r[off + tid];
        else if (tid < 128) ks[tid-64]   = k[off + tid - 64];
        else if (tid < 192) vs[tid-128]  = v[off + tid - 128];
        __syncthreads();
        if (tid < 32) {
            float p = rs[tid]*us[tid]*ks[tid] + rs[tid+32]*us[tid+32]*ks[tid+32];
            #pragma unroll
            for (int o = 16; o > 0; o >>= 1) p += __shfl_xor_sync(0xffffffffu, p, o);
            if (tid == 0) csh = p;
        }
        __syncthreads();
        float vj = vs[j];
        float yp = 0.f;
        #pragma unroll
        for (int ii = 0; ii < 16; ii++) {
            yp = fmaf(rs[i0+ii], s[ii], yp);
            s[ii] = fmaf(ew[ii], s[ii], ks[i0+ii]*vj);
        }
        yp += __shfl_xor_sync(0xffffffffu, yp, 1);
        yp += __shfl_xor_sync(0xffffffffu, yp, 2);
        if (q == 0) y[off + j] = yp + csh * vj;
        __syncthreads();
    }
}

// ---------------- groupnorm(y/8)*silu(g) -> z hi/lo bf16 --------------------
__global__ void gngate_kernel(const float* __restrict__ y, const float* __restrict__ g,
                              const float* __restrict__ w, const float* __restrict__ b,
                              __nv_bfloat16* __restrict__ zh, __nv_bfloat16* __restrict__ zl) {
    int idx = blockIdx.x;              // row*H + h
    int h = idx & (Hq-1);
    size_t off = (size_t)(idx >> 4) * Cq + h * 64;
    int lane = threadIdx.x;
    float y0 = y[off + lane]      * 0.125f;
    float y1 = y[off + lane + 32] * 0.125f;
    float s = y0 + y1, s2 = y0*y0 + y1*y1;
    #pragma unroll
    for (int o = 16; o > 0; o >>= 1) {
        s  += __shfl_xor_sync(0xffffffffu, s, o);
        s2 += __shfl_xor_sync(0xffffffffu, s2, o);
    }
    float mu = s * (1.f/64.f);
    float inv = rsqrtf(s2*(1.f/64.f) - mu*mu + EPSq);
    int c0 = h*64 + lane;
    float g0 = g[off + lane];
    float g1 = g[off + lane + 32];
    float si0 = g0 / (1.f + __expf(-g0));
    float si1 = g1 / (1.f + __expf(-g1));
    float z0 = ((y0-mu)*inv*w[c0]    + b[c0])    * si0;
    float z1 = ((y1-mu)*inv*w[c0+32] + b[c0+32]) * si1;
    __nv_bfloat16 h0,l0,h1,l1;
    split2(z0,h0,l0); split2(z1,h1,l1);
    zh[off + lane]      = h0;  zl[off + lane]      = l0;
    zh[off + lane + 32] = h1;  zl[off + lane + 32] = l1;
}

// ---------------- launch ----------------------------------------------------
extern "C" void kernel_launch(void* const* d_in, const int* in_sizes, int n_in,
                              void* d_out, int out_size) {
    const float* x        = (const float*)d_in[0];
    const float* ln0_w    = (const float*)d_in[1];
    const float* ln0_b    = (const float*)d_in[2];
    const float* ln1_w    = (const float*)d_in[3];
    const float* ln1_b    = (const float*)d_in[4];
    const float* ln2_w    = (const float*)d_in[5];
    const float* ln2_b    = (const float*)d_in[6];
    const float* att_tmk  = (const float*)d_in[7];
    const float* att_tmv  = (const float*)d_in[8];
    const float* att_tmr  = (const float*)d_in[9];
    const float* att_tmg  = (const float*)d_in[10];
    const float* att_decay= (const float*)d_in[11];
    const float* att_faaaa= (const float*)d_in[12];
    const float* att_Wr   = (const float*)d_in[13];
    const float* att_Wk   = (const float*)d_in[14];
    const float* att_Wv   = (const float*)d_in[15];
    const float* att_Wg   = (const float*)d_in[16];
    const float* att_Wo   = (const float*)d_in[17];
    const float* lnx_w    = (const float*)d_in[18];
    const float* lnx_b    = (const float*)d_in[19];
    const float* ffn_tmk  = (const float*)d_in[20];
    const float* ffn_tmr  = (const float*)d_in[21];
    const float* ffn_Wk   = (const float*)d_in[22];
    const float* ffn_Wr   = (const float*)d_in[23];
    const float* ffn_Wv   = (const float*)d_in[24];
    float* out = (float*)d_out;

    float *x0,*xn,*r_,*k_,*v_,*g_,*y_,*x1,*kv;
    cudaGetSymbolAddress((void**)&x0, g_x0);
    cudaGetSymbolAddress((void**)&xn, g_xn);
    cudaGetSymbolAddress((void**)&r_, g_r);
    cudaGetSymbolAddress((void**)&k_, g_k);
    cudaGetSymbolAddress((void**)&v_, g_v);
    cudaGetSymbolAddress((void**)&g_, g_g);
    cudaGetSymbolAddress((void**)&y_, g_y);
    cudaGetSymbolAddress((void**)&x1, g_x1);
    cudaGetSymbolAddress((void**)&kv, g_kv);

    __nv_bfloat16 *xrh,*xrl,*xkh,*xkl,*xvh,*xvl,*xgh,*xgl,*kfh,*kfl;
    __nv_bfloat16 *wrh,*wrl,*wkh,*wkl,*wvh,*wvl,*wgh,*wgl,*woh,*wol,*fkh,*fkl,*frh,*frl,*fvh,*fvl;
    cudaGetSymbolAddress((void**)&xrh, g_xrh); cudaGetSymbolAddress((void**)&xrl, g_xrl);
    cudaGetSymbolAddress((void**)&xkh, g_xkh); cudaGetSymbolAddress((void**)&xkl, g_xkl);
    cudaGetSymbolAddress((void**)&xvh, g_xvh); cudaGetSymbolAddress((void**)&xvl, g_xvl);
    cudaGetSymbolAddress((void**)&xgh, g_xgh); cudaGetSymbolAddress((void**)&xgl, g_xgl);
    cudaGetSymbolAddress((void**)&kfh, g_kfh); cudaGetSymbolAddress((void**)&kfl, g_kfl);
    cudaGetSymbolAddress((void**)&wrh, g_wrh); cudaGetSymbolAddress((void**)&wrl, g_wrl);
    cudaGetSymbolAddress((void**)&wkh, g_wkh); cudaGetSymbolAddress((void**)&wkl, g_wkl);
    cudaGetSymbolAddress((void**)&wvh, g_wvh); cudaGetSymbolAddress((void**)&wvl, g_wvl);
    cudaGetSymbolAddress((void**)&wgh, g_wgh); cudaGetSymbolAddress((void**)&wgl, g_wgl);
    cudaGetSymbolAddress((void**)&woh, g_woh); cudaGetSymbolAddress((void**)&wol, g_wol);
    cudaGetSymbolAddress((void**)&fkh, g_fkh); cudaGetSymbolAddress((void**)&fkl, g_fkl);
    cudaGetSymbolAddress((void**)&frh, g_frh); cudaGetSymbolAddress((void**)&frl, g_frl);
    cudaGetSymbolAddress((void**)&fvh, g_fvh); cudaGetSymbolAddress((void**)&fvl, g_fvl);

    cudaFuncSetAttribute(gemm_tc<0>, cudaFuncAttributeMaxDynamicSharedMemorySize, GEMM_SMEM);
    cudaFuncSetAttribute(gemm_tc<1>, cudaFuncAttributeMaxDynamicSharedMemorySize, GEMM_SMEM);
    cudaFuncSetAttribute(gemm_tc<2>, cudaFuncAttributeMaxDynamicSharedMemorySize, GEMM_SMEM);
    cudaFuncSetAttribute(gemm_tc<3>, cudaFuncAttributeMaxDynamicSharedMemorySize, GEMM_SMEM);

    dim3 blk256(256);
    const int nCC = Cq*Cq/4, nFC = FFNq*Cq/4;
    dim3 gCC(Cq/128, ROWS/128);       // (8, 128)
    dim3 gCF(FFNq/128, ROWS/128);     // (28, 128)

    // Launch order arranged so launch index 5 (ncu -s 5 -c 1) is gemm_tc<0> (r proj).
    cvt_kernel<<<nCC/256, 256>>>(att_Wr, wrh, wrl, nCC);                       // 0
    ln01_kernel<<<ROWS, blk256>>>(x, ln0_w, ln0_b, ln1_w, ln1_b, x0, xn);      // 1
    mix4_kernel<<<ROWS, blk256>>>(xn, att_tmk, att_tmv, att_tmr, att_tmg,
                                  xkh, xkl, xvh, xvl, xrh, xrl, xgh, xgl);     // 2
    cvt_kernel<<<nCC/256, 256>>>(att_Wk, wkh, wkl, nCC);                       // 3
    cvt_kernel<<<nCC/256, 256>>>(att_Wv, wvh, wvl, nCC);                       // 4
    gemm_tc<0><<<gCC, 256, GEMM_SMEM>>>(xrh, xrl, wrh, wrl, r_, Cq, Cq,
                                        nullptr, nullptr, nullptr, nullptr);   // 5  <- profiled
    cvt_kernel<<<nCC/256, 256>>>(att_Wg, wgh, wgl, nCC);
    cvt_kernel<<<nCC/256, 256>>>(att_Wo, woh, wol, nCC);
    cvt_kernel<<<nFC/256, 256>>>(ffn_Wk, fkh, fkl, nFC);
    cvt_kernel<<<nCC/256, 256>>>(ffn_Wr, frh, frl, nCC);
    cvt_kernel<<<nFC/256, 256>>>(ffn_Wv, fvh, fvl, nFC);

    gemm_tc<0><<<gCC, 256, GEMM_SMEM>>>(xkh, xkl, wkh, wkl, k_, Cq, Cq, nullptr, nullptr, nullptr, nullptr);
    gemm_tc<0><<<gCC, 256, GEMM_SMEM>>>(xvh, xvl, wvh, wvl, v_, Cq, Cq, nullptr, nullptr, nullptr, nullptr);
    gemm_tc<0><<<gCC, 256, GEMM_SMEM>>>(xgh, xgl, wgh, wgl, g_, Cq, Cq, nullptr, nullptr, nullptr, nullptr);
    // wkv5 recurrence
    wkv5_kernel<<<Bq*Hq, blk256>>>(r_, k_, v_, att_decay, att_faaaa, y_);
    // groupnorm + gate -> z hi/lo (reuse xg buffers)
    gngate_kernel<<<ROWS*Hq, 32>>>(y_, g_, lnx_w, lnx_b, xgh, xgl);
    // output projection + residual
    gemm_tc<1><<<gCC, 256, GEMM_SMEM>>>(xgh, xgl, woh, wol, x1, Cq, Cq, x0, nullptr, nullptr, nullptr);
    // channel-mix
    ln_kernel<<<ROWS, blk256>>>(x1, ln2_w, ln2_b, xn);
    mix2_kernel<<<ROWS, blk256>>>(xn, ffn_tmk, ffn_tmr, xkh, xkl, xrh, xrl);
    gemm_tc<2><<<gCF, 256, GEMM_SMEM>>>(xkh, xkl, fkh, fkl, nullptr, FFNq, Cq, nullptr, nullptr, kfh, kfl);
    gemm_tc<0><<<gCC, 256, GEMM_SMEM>>>(kfh, kfl, fvh, fvl, kv, Cq, FFNq, nullptr, nullptr, nullptr, nullptr);
    gemm_tc<3><<<gCC, 256, GEMM_SMEM>>>(xrh, xrl, frh, frl, out, Cq, Cq, x1, kv, nullptr, nullptr);
}

// round 13
// speedup vs baseline: 2.7195x; 1.1626x over previous
#include <cuda_runtime.h>
#include <cuda_bf16.h>
#include <cstdint>
#include <math.h>

#define Bq 8
#define Tq 2048
#define Cq 1024
#define Hq 16
#define Nq 64
#define FFNq 3584
#define EPSq 1e-5f
#define ROWS (Bq*Tq)            // 16384

// ---------------- scratch (device globals; no cudaMalloc allowed) -----------
__device__ __align__(16) float g_x0 [ROWS*Cq];
__device__ __align__(16) float g_xn [ROWS*Cq];
__device__ __align__(16) float g_r  [ROWS*Cq];
__device__ __align__(16) float g_k  [ROWS*Cq];
__device__ __align__(16) float g_v  [ROWS*Cq];
__device__ __align__(16) float g_g  [ROWS*Cq];
__device__ __align__(16) float g_y  [ROWS*Cq];
__device__ __align__(16) float g_x1 [ROWS*Cq];
__device__ __align__(16) float g_kv [ROWS*Cq];
// bf16 hi/lo activation pairs
__device__ __align__(16) __nv_bfloat16 g_xrh[ROWS*Cq], g_xrl[ROWS*Cq];
__device__ __align__(16) __nv_bfloat16 g_xkh[ROWS*Cq], g_xkl[ROWS*Cq];
__device__ __align__(16) __nv_bfloat16 g_xvh[ROWS*Cq], g_xvl[ROWS*Cq];
__device__ __align__(16) __nv_bfloat16 g_xgh[ROWS*Cq], g_xgl[ROWS*Cq];   // reused for z
__device__ __align__(16) __nv_bfloat16 g_kfh[(size_t)ROWS*FFNq], g_kfl[(size_t)ROWS*FFNq];
// bf16 hi/lo weight pairs
__device__ __align__(16) __nv_bfloat16 g_wrh[Cq*Cq],  g_wrl[Cq*Cq];
__device__ __align__(16) __nv_bfloat16 g_wkh[Cq*Cq],  g_wkl[Cq*Cq];
__device__ __align__(16) __nv_bfloat16 g_wvh[Cq*Cq],  g_wvl[Cq*Cq];
__device__ __align__(16) __nv_bfloat16 g_wgh[Cq*Cq],  g_wgl[Cq*Cq];
__device__ __align__(16) __nv_bfloat16 g_woh[Cq*Cq],  g_wol[Cq*Cq];
__device__ __align__(16) __nv_bfloat16 g_fkh[FFNq*Cq],g_fkl[FFNq*Cq];
__device__ __align__(16) __nv_bfloat16 g_frh[Cq*Cq],  g_frl[Cq*Cq];
__device__ __align__(16) __nv_bfloat16 g_fvh[Cq*FFNq],g_fvl[Cq*FFNq];

// ---------------- helpers ----------------------------------------------------
__device__ __forceinline__ uint32_t smem_u32(const void* p) {
    uint32_t a;
    asm("{ .reg .u64 t; cvta.to.shared.u64 t, %1; cvt.u32.u64 %0, t; }" : "=r"(a) : "l"(p));
    return a;
}
__device__ __forceinline__ void cp16(uint32_t dst, const void* src) {
    asm volatile("cp.async.cg.shared.global [%0], [%1], 16;" :: "r"(dst), "l"(src) : "memory");
}
__device__ __forceinline__ void cp_commit() {
    asm volatile("cp.async.commit_group;" ::: "memory");
}
template<int N>
__device__ __forceinline__ void cp_wait() {
    asm volatile("cp.async.wait_group %0;" :: "n"(N) : "memory");
}
__device__ __forceinline__ void ldm4(uint32_t* r, uint32_t addr) {
    asm volatile("ldmatrix.sync.aligned.m8n8.x4.shared.b16 {%0,%1,%2,%3}, [%4];"
        : "=r"(r[0]), "=r"(r[1]), "=r"(r[2]), "=r"(r[3]) : "r"(addr));
}
__device__ __forceinline__ void mma16816(float* c, const uint32_t* a, const uint32_t* b) {
    asm volatile("mma.sync.aligned.m16n8k16.row.col.f32.bf16.bf16.f32 "
        "{%0,%1,%2,%3}, {%4,%5,%6,%7}, {%8,%9}, {%0,%1,%2,%3};"
        : "+f"(c[0]), "+f"(c[1]), "+f"(c[2]), "+f"(c[3])
        : "r"(a[0]), "r"(a[1]), "r"(a[2]), "r"(a[3]), "r"(b[0]), "r"(b[1]));
}
__device__ __forceinline__ void split2(float v, __nv_bfloat16& h, __nv_bfloat16& l) {
    h = __float2bfloat16(v);
    l = __float2bfloat16(v - __bfloat162float(h));
}
__device__ __forceinline__ uint32_t pack2(__nv_bfloat16 a, __nv_bfloat16 b) {
    return (uint32_t)__bfloat16_as_ushort(a) | ((uint32_t)__bfloat16_as_ushort(b) << 16);
}

// ---------------- mma.sync split-bf16 NT GEMM -------------------------------
// out[m][n] = epi( sum_k A[m][k]*W[n][k] ),  A,W given as bf16 hi/lo pairs.
// EPI: 0 plain fp32, 1 res+acc fp32, 2 relu(acc)^2 -> bf16 hi/lo, 3 res+sigmoid(acc)*aux
// CTA 128x128, 256 thr = 2(m) x 4(n) warps, warp 64x32. K-chunk 32 bf16.
#define KC 32
#define PSTR 80                      // padded smem row stride in bytes (40 bf16)
#define MATB (128*PSTR)              // 10240 bytes per matrix tile
#define STAGEB (4*MATB)              // 40960 per stage
#define GEMM_SMEM (2*STAGEB)         // 81920

__device__ __forceinline__ void stage_load(
    uint32_t stg, const __nv_bfloat16* Ah, const __nv_bfloat16* Al,
    const __nv_bfloat16* Bh, const __nv_bfloat16* Bl,
    int bm, int bn, int K, int k0, int tid)
{
    #pragma unroll
    for (int it = 0; it < 2; it++) {
        int idx = tid * 2 + it;        // 0..511
        int row = idx >> 2, seg = idx & 3;
        uint32_t d = stg + row * PSTR + seg * 16;
        size_t ao = (size_t)(bm + row) * K + k0 + seg * 8;
        size_t bo = (size_t)(bn + row) * K + k0 + seg * 8;
        cp16(d,          Ah + ao);
        cp16(d + MATB,   Al + ao);
        cp16(d + 2*MATB, Bh + bo);
        cp16(d + 3*MATB, Bl + bo);
    }
}

template<int EPI>
__global__ void __launch_bounds__(256, 2)
gemm_tc(const __nv_bfloat16* __restrict__ Ahi, const __nv_bfloat16* __restrict__ Alo,
        const __nv_bfloat16* __restrict__ Whi, const __nv_bfloat16* __restrict__ Wlo,
        float* __restrict__ out, int N, int K,
        const float* __restrict__ res, const float* __restrict__ aux,
        __nv_bfloat16* __restrict__ out_h, __nv_bfloat16* __restrict__ out_l)
{
    extern __shared__ __align__(16) char smem[];
    const uint32_t sb = smem_u32(smem);
    const int tid = threadIdx.x;
    const int bm = blockIdx.y * 128, bn = blockIdx.x * 128;
    const int warp = tid >> 5, lane = tid & 31;
    const int wm = warp >> 2, wn = warp & 3;           // 2 x 4 warp grid
    const int r = lane >> 2, c4 = lane & 3;

    float acc[4][4][4];
    #pragma unroll
    for (int i = 0; i < 4; i++)
        #pragma unroll
        for (int j = 0; j < 4; j++)
            #pragma unroll
            for (int q = 0; q < 4; q++) acc[i][j][q] = 0.f;

    const int nchunk = K / KC;
    stage_load(sb, Ahi, Alo, Whi, Wlo, bm, bn, K, 0, tid);
    cp_commit();

    // ldmatrix lane-address offsets (bytes within a matrix tile)
    const int aRow = wm*64 + (lane & 7) + ((lane >> 3) & 1) * 8;
    const uint32_t aOff = (uint32_t)aRow * PSTR + (lane >> 4) * 16;
    const int bRow = wn*32 + (lane & 7) + (lane >> 4) * 8;
    const uint32_t bOff = (uint32_t)bRow * PSTR + ((lane >> 3) & 1) * 16;

    for (int c = 0; c < nchunk; c++) {
        if (c + 1 < nchunk) {
            stage_load(sb + ((c+1)&1)*STAGEB, Ahi, Alo, Whi, Wlo, bm, bn, K, (c+1)*KC, tid);
            cp_commit();
            cp_wait<1>();
        } else {
            cp_wait<0>();
        }
        __syncthreads();
        const uint32_t st = sb + (c & 1) * STAGEB;
        #pragma unroll
        for (int ks = 0; ks < 2; ks++) {
            const uint32_t ko = ks * 32;               // 16 bf16 = 32 bytes
            uint32_t bh[4][2], bl[4][2];
            #pragma unroll
            for (int ntp = 0; ntp < 2; ntp++) {
                uint32_t t[4];
                ldm4(t, st + 2*MATB + bOff + ntp*16*PSTR + ko);
                bh[2*ntp][0] = t[0]; bh[2*ntp][1] = t[1];
                bh[2*ntp+1][0] = t[2]; bh[2*ntp+1][1] = t[3];
                ldm4(t, st + 3*MATB + bOff + ntp*16*PSTR + ko);
                bl[2*ntp][0] = t[0]; bl[2*ntp][1] = t[1];
                bl[2*ntp+1][0] = t[2]; bl[2*ntp+1][1] = t[3];
            }
            #pragma unroll
            for (int mt = 0; mt < 4; mt++) {
                uint32_t ah[4], al[4];
                ldm4(ah, st + aOff + mt*16*PSTR + ko);
                ldm4(al, st + MATB + aOff + mt*16*PSTR + ko);
                #pragma unroll
                for (int nt = 0; nt < 4; nt++) {
                    mma16816(acc[mt][nt], ah, bh[nt]);
                    mma16816(acc[mt][nt], ah, bl[nt]);
                    mma16816(acc[mt][nt], al, bh[nt]);
                }
            }
        }
        __syncthreads();
    }

    // epilogue
    #pragma unroll
    for (int mt = 0; mt < 4; mt++) {
        #pragma unroll
        for (int nt = 0; nt < 4; nt++) {
            const int m0 = bm + wm*64 + mt*16 + r;
            const int n0 = bn + wn*32 + nt*8 + c4*2;
            #pragma unroll
            for (int half = 0; half < 2; half++) {
                const int m_ = m0 + half*8;
                const size_t ob = (size_t)m_ * N + n0;
                float v0 = acc[mt][nt][half*2], v1 = acc[mt][nt][half*2+1];
                if (EPI == 0) {
                    *(float2*)(out + ob) = make_float2(v0, v1);
                } else if (EPI == 1) {
                    float2 rv = *(const float2*)(res + ob);
                    *(float2*)(out + ob) = make_float2(rv.x + v0, rv.y + v1);
                } else if (EPI == 3) {
                    float2 rv = *(const float2*)(res + ob);
                    float2 av = *(const float2*)(aux + ob);
                    float s0 = 1.f/(1.f + __expf(-v0));
                    float s1 = 1.f/(1.f + __expf(-v1));
                    *(float2*)(out + ob) = make_float2(rv.x + s0*av.x, rv.y + s1*av.y);
                } else { // relu^2 -> bf16 hi/lo
                    float t0 = fmaxf(v0, 0.f); t0 *= t0;
                    float t1 = fmaxf(v1, 0.f); t1 *= t1;
                    __nv_bfloat16 h0,l0,h1,l1;
                    split2(t0,h0,l0); split2(t1,h1,l1);
                    *(uint32_t*)(out_h + ob) = pack2(h0,h1);
                    *(uint32_t*)(out_l + ob) = pack2(l0,l1);
                }
            }
        }
    }
}

// ---------------- block reduce (sum pair) over 256 threads ------------------
__device__ __forceinline__ void block_reduce_2(float& a, float& b) {
    __shared__ float sa[8], sb2[8];
    int lane = threadIdx.x & 31, wid = threadIdx.x >> 5;
    #pragma unroll
    for (int o = 16; o > 0; o >>= 1) {
        a += __shfl_xor_sync(0xffffffffu, a, o);
        b += __shfl_xor_sync(0xffffffffu, b, o);
    }
    if (lane == 0) { sa[wid] = a; sb2[wid] = b; }
    __syncthreads();
    a = 0.f; b = 0.f;
    #pragma unroll
    for (int i = 0; i < 8; i++) { a += sa[i]; b += sb2[i]; }
    __syncthreads();
}

// ---------------- fused ln0 + ln1 -------------------------------------------
__global__ void ln01_kernel(const float* __restrict__ x,
                            const float* __restrict__ w0, const float* __restrict__ b0,
                            const float* __restrict__ w1, const float* __restrict__ b1,
                            float* __restrict__ x0, float* __restrict__ xn) {
    int row = blockIdx.x, tid = threadIdx.x;
    size_t off = (size_t)row * Cq;
    float v[4]; float s = 0.f, s2 = 0.f;
    #pragma unroll
    for (int i = 0; i < 4; i++) {
        v[i] = x[off + tid + i*256];
        s += v[i]; s2 += v[i]*v[i];
    }
    block_reduce_2(s, s2);
    float mu = s * (1.f/Cq);
    float inv = rsqrtf(s2*(1.f/Cq) - mu*mu + EPSq);
    float o[4]; s = 0.f; s2 = 0.f;
    #pragma unroll
    for (int i = 0; i < 4; i++) {
        int c = tid + i*256;
        o[i] = (v[i]-mu)*inv*w0[c] + b0[c];
        x0[off + c] = o[i];
        s += o[i]; s2 += o[i]*o[i];
    }
    block_reduce_2(s, s2);
    mu = s * (1.f/Cq);
    inv = rsqrtf(s2*(1.f/Cq) - mu*mu + EPSq);
    #pragma unroll
    for (int i = 0; i < 4; i++) {
        int c = tid + i*256;
        xn[off + c] = (o[i]-mu)*inv*w1[c] + b1[c];
    }
}

__global__ void ln_kernel(const float* __restrict__ x,
                          const float* __restrict__ w, const float* __restrict__ b,
                          float* __restrict__ out) {
    int row = blockIdx.x, tid = threadIdx.x;
    size_t off = (size_t)row * Cq;
    float v[4]; float s = 0.f, s2 = 0.f;
    #pragma unroll
    for (int i = 0; i < 4; i++) {
        v[i] = x[off + tid + i*256];
        s += v[i]; s2 += v[i]*v[i];
    }
    block_reduce_2(s, s2);
    float mu = s * (1.f/Cq);
    float inv = rsqrtf(s2*(1.f/Cq) - mu*mu + EPSq);
    #pragma unroll
    for (int i = 0; i < 4; i++) {
        int c = tid + i*256;
        out[off + c] = (v[i]-mu)*inv*w[c] + b[c];
    }
}

// ---------------- token-shift mixes (emit bf16 hi/lo) -----------------------
__global__ void mix4_kernel(const float* __restrict__ xn,
                            const float* __restrict__ tmk, const float* __restrict__ tmv,
                            const float* __restrict__ tmr, const float* __restrict__ tmg,
                            __nv_bfloat16* __restrict__ xkh, __nv_bfloat16* __restrict__ xkl,
                            __nv_bfloat16* __restrict__ xvh, __nv_bfloat16* __restrict__ xvl,
                            __nv_bfloat16* __restrict__ xrh, __nv_bfloat16* __restrict__ xrl,
                            __nv_bfloat16* __restrict__ xgh, __nv_bfloat16* __restrict__ xgl) {
    int row = blockIdx.x, tid = threadIdx.x;
    int t = row & (Tq-1);
    size_t off = (size_t)row * Cq;
    #pragma unroll
    for (int i = 0; i < 2; i++) {
        int c = (tid + i*256) * 2;
        float2 cur = *(const float2*)(xn + off + c);
        float2 prv = (t > 0) ? *(const float2*)(xn + off - Cq + c) : make_float2(0.f, 0.f);
        float2 mk = *(const float2*)(tmk + c), mv = *(const float2*)(tmv + c);
        float2 mr = *(const float2*)(tmr + c), mg = *(const float2*)(tmg + c);
        __nv_bfloat16 h0,l0,h1,l1;
        float a0 = cur.x*mk.x + prv.x*(1.f-mk.x), a1 = cur.y*mk.y + prv.y*(1.f-mk.y);
        split2(a0,h0,l0); split2(a1,h1,l1);
        *(uint32_t*)(xkh+off+c) = pack2(h0,h1); *(uint32_t*)(xkl+off+c) = pack2(l0,l1);
        a0 = cur.x*mv.x + prv.x*(1.f-mv.x); a1 = cur.y*mv.y + prv.y*(1.f-mv.y);
        split2(a0,h0,l0); split2(a1,h1,l1);
        *(uint32_t*)(xvh+off+c) = pack2(h0,h1); *(uint32_t*)(xvl+off+c) = pack2(l0,l1);
        a0 = cur.x*mr.x + prv.x*(1.f-mr.x); a1 = cur.y*mr.y + prv.y*(1.f-mr.y);
        split2(a0,h0,l0); split2(a1,h1,l1);
        *(uint32_t*)(xrh+off+c) = pack2(h0,h1); *(uint32_t*)(xrl+off+c) = pack2(l0,l1);
        a0 = cur.x*mg.x + prv.x*(1.f-mg.x); a1 = cur.y*mg.y + prv.y*(1.f-mg.y);
        split2(a0,h0,l0); split2(a1,h1,l1);
        *(uint32_t*)(xgh+off+c) = pack2(h0,h1); *(uint32_t*)(xgl+off+c) = pack2(l0,l1);
    }
}

__global__ void mix2_kernel(const float* __restrict__ xn,
                            const float* __restrict__ tmk, const float* __restrict__ tmr,
                            __nv_bfloat16* __restrict__ xkh, __nv_bfloat16* __restrict__ xkl,
                            __nv_bfloat16* __restrict__ xrh, __nv_bfloat16* __restrict__ xrl) {
    int row = blockIdx.x, tid = threadIdx.x;
    int t = row & (Tq-1);
    size_t off = (size_t)row * Cq;
    #pragma unroll
    for (int i = 0; i < 2; i++) {
        int c = (tid + i*256) * 2;
        float2 cur = *(const float2*)(xn + off + c);
        float2 prv = (t > 0) ? *(const float2*)(xn + off - Cq + c) : make_float2(0.f, 0.f);
        float2 mk = *(const float2*)(tmk + c), mr = *(const float2*)(tmr + c);
        __nv_bfloat16 h0,l0,h1,l1;
        float a0 = cur.x*mk.x + prv.x*(1.f-mk.x), a1 = cur.y*mk.y + prv.y*(1.f-mk.y);
        split2(a0,h0,l0); split2(a1,h1,l1);
        *(uint32_t*)(xkh+off+c) = pack2(h0,h1); *(uint32_t*)(xkl+off+c) = pack2(l0,l1);
        a0 = cur.x*mr.x + prv.x*(1.f-mr.x); a1 = cur.y*mr.y + prv.y*(1.f-mr.y);
        split2(a0,h0,l0); split2(a1,h1,l1);
        *(uint32_t*)(xrh+off+c) = pack2(h0,h1); *(uint32_t*)(xrl+off+c) = pack2(l0,l1);
    }
}

// ---------------- weight fp32 -> bf16 hi/lo ----------------------------------
__global__ void cvt_kernel(const float* __restrict__ in,
                           __nv_bfloat16* __restrict__ h, __nv_bfloat16* __restrict__ l,
                           int n4) {
    int i = blockIdx.x * 256 + threadIdx.x;
    if (i >= n4) return;
    float4 v = ((const float4*)in)[i];
    __nv_bfloat16 h0,l0,h1,l1,h2,l2,h3,l3;
    split2(v.x,h0,l0); split2(v.y,h1,l1); split2(v.z,h2,l2); split2(v.w,h3,l3);
    ((uint2*)h)[i] = make_uint2(pack2(h0,h1), pack2(h2,h3));
    ((uint2*)l)[i] = make_uint2(pack2(l0,l1), pack2(l2,l3));
}

// ---------------- wkv5 recurrence (prefetch + single barrier per step) ------
// y_j = sum_i r_i*S_ij + (sum_i r_i*u_i*k_i)*v_j ; S_ij = ew_i*S_ij + k_i*v_j
__global__ void __launch_bounds__(256)
wkv5_kernel(const float* __restrict__ r, const float* __restrict__ k,
            const float* __restrict__ v, const float* __restrict__ w,
            const float* __restrict__ u, float* __restrict__ y) {
    int bh = blockIdx.x;
    int b = bh >> 4, h = bh & 15;
    int tid = threadIdx.x;
    int j = tid >> 2, q = tid & 3, i0 = q * 16;

    __shared__ float rs[2][64], ks[2][64], vs[2][64];

    float s[16], ew[16], us[16];
    #pragma unroll
    for (int ii = 0; ii < 16; ii++) {
        s[ii] = 0.f;
        ew[ii] = expf(-expf(w[h*64 + i0 + ii]));
        us[ii] = u[h*64 + i0 + ii];
    }

    size_t base = (size_t)b * Tq * Cq + h * 64;
    // prefetch t=0 into register
    float pre = 0.f;
    {
        size_t off0 = base;
        if (tid < 64)        pre = r[off0 + tid];
        else if (tid < 128)  pre = k[off0 + tid - 64];
        else if (tid < 192)  pre = v[off0 + tid - 128];
    }

    for (int t = 0; t < Tq; t++) {
        int bufi = t & 1;
        // store prefetched values for step t
        if (tid < 64)        rs[bufi][tid]      = pre;
        else if (tid < 128)  ks[bufi][tid-64]   = pre;
        else if (tid < 192)  vs[bufi][tid-128]  = pre;
        // issue prefetch for t+1 (completes during compute below)
        if (t + 1 < Tq) {
            size_t offn = base + (size_t)(t+1) * Cq;
            if (tid < 64)        pre = r[offn + tid];
            else if (tid < 128)  pre = k[offn + tid - 64];
            else if (tid < 192)  pre = v[offn + tid - 128];
        }
        __syncthreads();

        float vj = vs[bufi][j];
        float yp = 0.f, cs = 0.f;
        #pragma unroll
        for (int ii = 0; ii < 16; ii++) {
            float rv = rs[bufi][i0+ii];
            float kv_ = ks[bufi][i0+ii];
            yp = fmaf(rv, s[ii], yp);
            cs = fmaf(rv * us[ii], kv_, cs);
            s[ii] = fmaf(ew[ii], s[ii], kv_ * vj);
        }
        // quad reduction (lanes xor 1,2 share the same j)
        yp += __shfl_xor_sync(0xffffffffu, yp, 1);
        yp += __shfl_xor_sync(0xffffffffu, yp, 2);
        cs += __shfl_xor_sync(0xffffffffu, cs, 1);
        cs += __shfl_xor_sync(0xffffffffu, cs, 2);
        if (q == 0) y[base + (size_t)t * Cq + j] = yp + cs * vj;
        // NOTE: no second barrier needed — buffer bufi is next written at step
        // t+2, and every thread passes the t+1 barrier after finishing this
        // compute, which orders compute(t) before store(t+2).
    }
}

// ---------------- groupnorm(y/8)*silu(g) -> z hi/lo bf16 --------------------
__global__ void gngate_kernel(const float* __restrict__ y, const float* __restrict__ g,
                              const float* __restrict__ w, const float* __restrict__ b,
                              __nv_bfloat16* __restrict__ zh, __nv_bfloat16* __restrict__ zl) {
    int idx = blockIdx.x;              // row*H + h
    int h = idx & (Hq-1);
    size_t off = (size_t)(idx >> 4) * Cq + h * 64;
    int lane = threadIdx.x;
    float y0 = y[off + lane]      * 0.125f;
    float y1 = y[off + lane + 32] * 0.125f;
    float s = y0 + y1, s2 = y0*y0 + y1*y1;
    #pragma unroll
    for (int o = 16; o > 0; o >>= 1) {
        s  += __shfl_xor_sync(0xffffffffu, s, o);
        s2 += __shfl_xor_sync(0xffffffffu, s2, o);
    }
    float mu = s * (1.f/64.f);
    float inv = rsqrtf(s2*(1.f/64.f) - mu*mu + EPSq);
    int c0 = h*64 + lane;
    float g0 = g[off + lane];
    float g1 = g[off + lane + 32];
    float si0 = g0 / (1.f + __expf(-g0));
    float si1 = g1 / (1.f + __expf(-g1));
    float z0 = ((y0-mu)*inv*w[c0]    + b[c0])    * si0;
    float z1 = ((y1-mu)*inv*w[c0+32] + b[c0+32]) * si1;
    __nv_bfloat16 h0,l0,h1,l1;
    split2(z0,h0,l0); split2(z1,h1,l1);
    zh[off + lane]      = h0;  zl[off + lane]      = l0;
    zh[off + lane + 32] = h1;  zl[off + lane + 32] = l1;
}

// ---------------- launch ----------------------------------------------------
extern "C" void kernel_launch(void* const* d_in, const int* in_sizes, int n_in,
                              void* d_out, int out_size) {
    const float* x        = (const float*)d_in[0];
    const float* ln0_w    = (const float*)d_in[1];
    const float* ln0_b    = (const float*)d_in[2];
    const float* ln1_w    = (const float*)d_in[3];
    const float* ln1_b    = (const float*)d_in[4];
    const float* ln2_w    = (const float*)d_in[5];
    const float* ln2_b    = (const float*)d_in[6];
    const float* att_tmk  = (const float*)d_in[7];
    const float* att_tmv  = (const float*)d_in[8];
    const float* att_tmr  = (const float*)d_in[9];
    const float* att_tmg  = (const float*)d_in[10];
    const float* att_decay= (const float*)d_in[11];
    const float* att_faaaa= (const float*)d_in[12];
    const float* att_Wr   = (const float*)d_in[13];
    const float* att_Wk   = (const float*)d_in[14];
    const float* att_Wv   = (const float*)d_in[15];
    const float* att_Wg   = (const float*)d_in[16];
    const float* att_Wo   = (const float*)d_in[17];
    const float* lnx_w    = (const float*)d_in[18];
    const float* lnx_b    = (const float*)d_in[19];
    const float* ffn_tmk  = (const float*)d_in[20];
    const float* ffn_tmr  = (const float*)d_in[21];
    const float* ffn_Wk   = (const float*)d_in[22];
    const float* ffn_Wr   = (const float*)d_in[23];
    const float* ffn_Wv   = (const float*)d_in[24];
    float* out = (float*)d_out;

    float *x0,*xn,*r_,*k_,*v_,*g_,*y_,*x1,*kv;
    cudaGetSymbolAddress((void**)&x0, g_x0);
    cudaGetSymbolAddress((void**)&xn, g_xn);
    cudaGetSymbolAddress((void**)&r_, g_r);
    cudaGetSymbolAddress((void**)&k_, g_k);
    cudaGetSymbolAddress((void**)&v_, g_v);
    cudaGetSymbolAddress((void**)&g_, g_g);
    cudaGetSymbolAddress((void**)&y_, g_y);
    cudaGetSymbolAddress((void**)&x1, g_x1);
    cudaGetSymbolAddress((void**)&kv, g_kv);

    __nv_bfloat16 *xrh,*xrl,*xkh,*xkl,*xvh,*xvl,*xgh,*xgl,*kfh,*kfl;
    __nv_bfloat16 *wrh,*wrl,*wkh,*wkl,*wvh,*wvl,*wgh,*wgl,*woh,*wol,*fkh,*fkl,*frh,*frl,*fvh,*fvl;
    cudaGetSymbolAddress((void**)&xrh, g_xrh); cudaGetSymbolAddress((void**)&xrl, g_xrl);
    cudaGetSymbolAddress((void**)&xkh, g_xkh); cudaGetSymbolAddress((void**)&xkl, g_xkl);
    cudaGetSymbolAddress((void**)&xvh, g_xvh); cudaGetSymbolAddress((void**)&xvl, g_xvl);
    cudaGetSymbolAddress((void**)&xgh, g_xgh); cudaGetSymbolAddress((void**)&xgl, g_xgl);
    cudaGetSymbolAddress((void**)&kfh, g_kfh); cudaGetSymbolAddress((void**)&kfl, g_kfl);
    cudaGetSymbolAddress((void**)&wrh, g_wrh); cudaGetSymbolAddress((void**)&wrl, g_wrl);
    cudaGetSymbolAddress((void**)&wkh, g_wkh); cudaGetSymbolAddress((void**)&wkl, g_wkl);
    cudaGetSymbolAddress((void**)&wvh, g_wvh); cudaGetSymbolAddress((void**)&wvl, g_wvl);
    cudaGetSymbolAddress((void**)&wgh, g_wgh); cudaGetSymbolAddress((void**)&wgl, g_wgl);
    cudaGetSymbolAddress((void**)&woh, g_woh); cudaGetSymbolAddress((void**)&wol, g_wol);
    cudaGetSymbolAddress((void**)&fkh, g_fkh); cudaGetSymbolAddress((void**)&fkl, g_fkl);
    cudaGetSymbolAddress((void**)&frh, g_frh); cudaGetSymbolAddress((void**)&frl, g_frl);
    cudaGetSymbolAddress((void**)&fvh, g_fvh); cudaGetSymbolAddress((void**)&fvl, g_fvl);

    cudaFuncSetAttribute(gemm_tc<0>, cudaFuncAttributeMaxDynamicSharedMemorySize, GEMM_SMEM);
    cudaFuncSetAttribute(gemm_tc<1>, cudaFuncAttributeMaxDynamicSharedMemorySize, GEMM_SMEM);
    cudaFuncSetAttribute(gemm_tc<2>, cudaFuncAttributeMaxDynamicSharedMemorySize, GEMM_SMEM);
    cudaFuncSetAttribute(gemm_tc<3>, cudaFuncAttributeMaxDynamicSharedMemorySize, GEMM_SMEM);

    dim3 blk256(256);
    const int nCC = Cq*Cq/4, nFC = FFNq*Cq/4;
    dim3 gCC(Cq/128, ROWS/128);       // (8, 128)
    dim3 gCF(FFNq/128, ROWS/128);     // (28, 128)

    // Harness injects one launch before ours; ncu -s 5 -c 1 captures OUR index 4.
    cvt_kernel<<<nCC/256, 256>>>(att_Wr, wrh, wrl, nCC);                       // 0
    ln01_kernel<<<ROWS, blk256>>>(x, ln0_w, ln0_b, ln1_w, ln1_b, x0, xn);      // 1
    mix4_kernel<<<ROWS, blk256>>>(xn, att_tmk, att_tmv, att_tmr, att_tmg,
                                  xkh, xkl, xvh, xvl, xrh, xrl, xgh, xgl);     // 2
    cvt_kernel<<<nCC/256, 256>>>(att_Wk, wkh, wkl, nCC);                       // 3
    gemm_tc<0><<<gCC, 256, GEMM_SMEM>>>(xrh, xrl, wrh, wrl, r_, Cq, Cq,
                                        nullptr, nullptr, nullptr, nullptr);   // 4 <- profiled
    gemm_tc<0><<<gCC, 256, GEMM_SMEM>>>(xkh, xkl, wkh, wkl, k_, Cq, Cq,
                                        nullptr, nullptr, nullptr, nullptr);   // 5 (fallback slot)
    cvt_kernel<<<nCC/256, 256>>>(att_Wv, wvh, wvl, nCC);
    cvt_kernel<<<nCC/256, 256>>>(att_Wg, wgh, wgl, nCC);
    cvt_kernel<<<nCC/256, 256>>>(att_Wo, woh, wol, nCC);
    cvt_kernel<<<nFC/256, 256>>>(ffn_Wk, fkh, fkl, nFC);
    cvt_kernel<<<nCC/256, 256>>>(ffn_Wr, frh, frl, nCC);
    cvt_kernel<<<nFC/256, 256>>>(ffn_Wv, fvh, fvl, nFC);

    gemm_tc<0><<<gCC, 256, GEMM_SMEM>>>(xvh, xvl, wvh, wvl, v_, Cq, Cq, nullptr, nullptr, nullptr, nullptr);
    gemm_tc<0><<<gCC, 256, GEMM_SMEM>>>(xgh, xgl, wgh, wgl, g_, Cq, Cq, nullptr, nullptr, nullptr, nullptr);
    // wkv5 recurrence
    wkv5_kernel<<<Bq*Hq, blk256>>>(r_, k_, v_, att_decay, att_faaaa, y_);
    // groupnorm + gate -> z hi/lo (reuse xg buffers)
    gngate_kernel<<<ROWS*Hq, 32>>>(y_, g_, lnx_w, lnx_b, xgh, xgl);
    // output projection + residual
    gemm_tc<1><<<gCC, 256, GEMM_SMEM>>>(xgh, xgl, woh, wol, x1, Cq, Cq, x0, nullptr, nullptr, nullptr);
    // channel-mix
    ln_kernel<<<ROWS, blk256>>>(x1, ln2_w, ln2_b, xn);
    mix2_kernel<<<ROWS, blk256>>>(xn, ffn_tmk, ffn_tmr, xkh, xkl, xrh, xrl);
    gemm_tc<2><<<gCF, 256, GEMM_SMEM>>>(xkh, xkl, fkh, fkl, nullptr, FFNq, Cq, nullptr, nullptr, kfh, kfl);
    gemm_tc<0><<<gCC, 256, GEMM_SMEM>>>(kfh, kfl, fvh, fvl, kv, Cq, FFNq, nullptr, nullptr, nullptr, nullptr);
    gemm_tc<3><<<gCC, 256, GEMM_SMEM>>>(xrh, xrl, frh, frl, out, Cq, Cq, x1, kv, nullptr, nullptr);
}

// round 14
// speedup vs baseline: 3.4533x; 1.2698x over previous
#include <cuda_runtime.h>
#include <cuda_fp16.h>
#include <cstdint>
#include <math.h>

#define Bq 8
#define Tq 2048
#define Cq 1024
#define Hq 16
#define Nq 64
#define FFNq 3584
#define EPSq 1e-5f
#define ROWS (Bq*Tq)            // 16384

// ---------------- scratch (device globals; no cudaMalloc allowed) -----------
__device__ __align__(16) float g_x0 [ROWS*Cq];
__device__ __align__(16) float g_xn [ROWS*Cq];
__device__ __align__(16) float g_r  [ROWS*Cq];
__device__ __align__(16) float g_k  [ROWS*Cq];
__device__ __align__(16) float g_v  [ROWS*Cq];
__device__ __align__(16) float g_g  [ROWS*Cq];
__device__ __align__(16) float g_y  [ROWS*Cq];
__device__ __align__(16) float g_x1 [ROWS*Cq];
__device__ __align__(16) float g_kv [ROWS*Cq];
// fp16 hi/lo activation pairs
__device__ __align__(16) __half g_xrh[ROWS*Cq], g_xrl[ROWS*Cq];
__device__ __align__(16) __half g_xkh[ROWS*Cq], g_xkl[ROWS*Cq];
__device__ __align__(16) __half g_xvh[ROWS*Cq], g_xvl[ROWS*Cq];
__device__ __align__(16) __half g_xgh[ROWS*Cq], g_xgl[ROWS*Cq];   // reused for z
__device__ __align__(16) __half g_kfh[(size_t)ROWS*FFNq], g_kfl[(size_t)ROWS*FFNq];
// fp16 single weights
__device__ __align__(16) __half g_wr[Cq*Cq];
__device__ __align__(16) __half g_wk[Cq*Cq];
__device__ __align__(16) __half g_wv[Cq*Cq];
__device__ __align__(16) __half g_wg[Cq*Cq];
__device__ __align__(16) __half g_wo[Cq*Cq];
__device__ __align__(16) __half g_fk[FFNq*Cq];
__device__ __align__(16) __half g_fr[Cq*Cq];
__device__ __align__(16) __half g_fv[Cq*FFNq];

// ---------------- helpers ----------------------------------------------------
__device__ __forceinline__ uint32_t smem_u32(const void* p) {
    uint32_t a;
    asm("{ .reg .u64 t; cvta.to.shared.u64 t, %1; cvt.u32.u64 %0, t; }" : "=r"(a) : "l"(p));
    return a;
}
__device__ __forceinline__ void cp16(uint32_t dst, const void* src) {
    asm volatile("cp.async.cg.shared.global [%0], [%1], 16;" :: "r"(dst), "l"(src) : "memory");
}
__device__ __forceinline__ void cp_commit() {
    asm volatile("cp.async.commit_group;" ::: "memory");
}
template<int N>
__device__ __forceinline__ void cp_wait() {
    asm volatile("cp.async.wait_group %0;" :: "n"(N) : "memory");
}
__device__ __forceinline__ void ldm4(uint32_t* r, uint32_t addr) {
    asm volatile("ldmatrix.sync.aligned.m8n8.x4.shared.b16 {%0,%1,%2,%3}, [%4];"
        : "=r"(r[0]), "=r"(r[1]), "=r"(r[2]), "=r"(r[3]) : "r"(addr));
}
__device__ __forceinline__ void mma16816(float* c, const uint32_t* a, const uint32_t* b) {
    asm volatile("mma.sync.aligned.m16n8k16.row.col.f32.f16.f16.f32 "
        "{%0,%1,%2,%3}, {%4,%5,%6,%7}, {%8,%9}, {%0,%1,%2,%3};"
        : "+f"(c[0]), "+f"(c[1]), "+f"(c[2]), "+f"(c[3])
        : "r"(a[0]), "r"(a[1]), "r"(a[2]), "r"(a[3]), "r"(b[0]), "r"(b[1]));
}
__device__ __forceinline__ void split2h(float v, __half& h, __half& l) {
    h = __float2half_rn(v);
    l = __float2half_rn(v - __half2float(h));
}
__device__ __forceinline__ uint32_t pack2h(__half a, __half b) {
    return (uint32_t)__half_as_ushort(a) | ((uint32_t)__half_as_ushort(b) << 16);
}

// ---------------- mma.sync split-fp16 NT GEMM -------------------------------
// out[m][n] = epi( sum_k A[m][k]*W[n][k] );  A as fp16 hi/lo pair, W single fp16.
// D = Ah*W + Al*W  (== (Ah+Al)*W; error = W fp16 quantization only ~1e-4)
// EPI: 0 plain fp32, 1 res+acc fp32, 2 relu(acc)^2 -> fp16 hi/lo, 3 res+sigmoid(acc)*aux
// CTA 128x128, 256 thr = 2(m) x 4(n) warps, warp 64x32. K-chunk 32 fp16.
#define KC 32
#define PSTR 80                      // padded smem row stride in bytes (40 fp16)
#define MATB (128*PSTR)              // 10240 bytes per matrix tile
#define STAGEB (3*MATB)              // 30720 per stage (Ah, Al, W)
#define GEMM_SMEM (2*STAGEB)         // 61440

__device__ __forceinline__ void stage_load(
    uint32_t stg, const __half* Ah, const __half* Al, const __half* W,
    int bm, int bn, int K, int k0, int tid)
{
    #pragma unroll
    for (int it = 0; it < 2; it++) {
        int idx = tid * 2 + it;        // 0..511
        int row = idx >> 2, seg = idx & 3;
        uint32_t d = stg + row * PSTR + seg * 16;
        size_t ao = (size_t)(bm + row) * K + k0 + seg * 8;
        size_t bo = (size_t)(bn + row) * K + k0 + seg * 8;
        cp16(d,          Ah + ao);
        cp16(d + MATB,   Al + ao);
        cp16(d + 2*MATB, W + bo);
    }
}

template<int EPI>
__global__ void __launch_bounds__(256, 2)
gemm_tc(const __half* __restrict__ Ahi, const __half* __restrict__ Alo,
        const __half* __restrict__ W,
        float* __restrict__ out, int N, int K,
        const float* __restrict__ res, const float* __restrict__ aux,
        __half* __restrict__ out_h, __half* __restrict__ out_l)
{
    extern __shared__ __align__(16) char smem[];
    const uint32_t sb = smem_u32(smem);
    const int tid = threadIdx.x;
    const int bm = blockIdx.y * 128, bn = blockIdx.x * 128;
    const int warp = tid >> 5, lane = tid & 31;
    const int wm = warp >> 2, wn = warp & 3;           // 2 x 4 warp grid
    const int r = lane >> 2, c4 = lane & 3;

    float acc[4][4][4];
    #pragma unroll
    for (int i = 0; i < 4; i++)
        #pragma unroll
        for (int j = 0; j < 4; j++)
            #pragma unroll
            for (int q = 0; q < 4; q++) acc[i][j][q] = 0.f;

    const int nchunk = K / KC;
    stage_load(sb, Ahi, Alo, W, bm, bn, K, 0, tid);
    cp_commit();

    // ldmatrix lane-address offsets (bytes within a matrix tile)
    const int aRow = wm*64 + (lane & 7) + ((lane >> 3) & 1) * 8;
    const uint32_t aOff = (uint32_t)aRow * PSTR + (lane >> 4) * 16;
    const int bRow = wn*32 + (lane & 7) + (lane >> 4) * 8;
    const uint32_t bOff = (uint32_t)bRow * PSTR + ((lane >> 3) & 1) * 16;

    for (int c = 0; c < nchunk; c++) {
        if (c + 1 < nchunk) {
            stage_load(sb + ((c+1)&1)*STAGEB, Ahi, Alo, W, bm, bn, K, (c+1)*KC, tid);
            cp_commit();
            cp_wait<1>();
        } else {
            cp_wait<0>();
        }
        __syncthreads();
        const uint32_t st = sb + (c & 1) * STAGEB;
        #pragma unroll
        for (int ks = 0; ks < 2; ks++) {
            const uint32_t ko = ks * 32;               // 16 fp16 = 32 bytes
            uint32_t bf[4][2];
            #pragma unroll
            for (int ntp = 0; ntp < 2; ntp++) {
                uint32_t t[4];
                ldm4(t, st + 2*MATB + bOff + ntp*16*PSTR + ko);
                bf[2*ntp][0] = t[0]; bf[2*ntp][1] = t[1];
                bf[2*ntp+1][0] = t[2]; bf[2*ntp+1][1] = t[3];
            }
            #pragma unroll
            for (int mt = 0; mt < 4; mt++) {
                uint32_t ah[4], al[4];
                ldm4(ah, st + aOff + mt*16*PSTR + ko);
                ldm4(al, st + MATB + aOff + mt*16*PSTR + ko);
                #pragma unroll
                for (int nt = 0; nt < 4; nt++) {
                    mma16816(acc[mt][nt], ah, bf[nt]);
                    mma16816(acc[mt][nt], al, bf[nt]);
                }
            }
        }
        __syncthreads();
    }

    // epilogue
    #pragma unroll
    for (int mt = 0; mt < 4; mt++) {
        #pragma unroll
        for (int nt = 0; nt < 4; nt++) {
            const int m0 = bm + wm*64 + mt*16 + r;
            const int n0 = bn + wn*32 + nt*8 + c4*2;
            #pragma unroll
            for (int half_ = 0; half_ < 2; half_++) {
                const int m_ = m0 + half_*8;
                const size_t ob = (size_t)m_ * N + n0;
                float v0 = acc[mt][nt][half_*2], v1 = acc[mt][nt][half_*2+1];
                if (EPI == 0) {
                    *(float2*)(out + ob) = make_float2(v0, v1);
                } else if (EPI == 1) {
                    float2 rv = *(const float2*)(res + ob);
                    *(float2*)(out + ob) = make_float2(rv.x + v0, rv.y + v1);
                } else if (EPI == 3) {
                    float2 rv = *(const float2*)(res + ob);
                    float2 av = *(const float2*)(aux + ob);
                    float s0 = 1.f/(1.f + __expf(-v0));
                    float s1 = 1.f/(1.f + __expf(-v1));
                    *(float2*)(out + ob) = make_float2(rv.x + s0*av.x, rv.y + s1*av.y);
                } else { // relu^2 -> fp16 hi/lo
                    float t0 = fmaxf(v0, 0.f); t0 *= t0;
                    float t1 = fmaxf(v1, 0.f); t1 *= t1;
                    __half h0,l0,h1,l1;
                    split2h(t0,h0,l0); split2h(t1,h1,l1);
                    *(uint32_t*)(out_h + ob) = pack2h(h0,h1);
                    *(uint32_t*)(out_l + ob) = pack2h(l0,l1);
                }
            }
        }
    }
}

// ---------------- block reduce (sum pair) over 256 threads ------------------
__device__ __forceinline__ void block_reduce_2(float& a, float& b) {
    __shared__ float sa[8], sb2[8];
    int lane = threadIdx.x & 31, wid = threadIdx.x >> 5;
    #pragma unroll
    for (int o = 16; o > 0; o >>= 1) {
        a += __shfl_xor_sync(0xffffffffu, a, o);
        b += __shfl_xor_sync(0xffffffffu, b, o);
    }
    if (lane == 0) { sa[wid] = a; sb2[wid] = b; }
    __syncthreads();
    a = 0.f; b = 0.f;
    #pragma unroll
    for (int i = 0; i < 8; i++) { a += sa[i]; b += sb2[i]; }
    __syncthreads();
}

// ---------------- fused ln0 + ln1 -------------------------------------------
__global__ void ln01_kernel(const float* __restrict__ x,
                            const float* __restrict__ w0, const float* __restrict__ b0,
                            const float* __restrict__ w1, const float* __restrict__ b1,
                            float* __restrict__ x0, float* __restrict__ xn) {
    int row = blockIdx.x, tid = threadIdx.x;
    size_t off = (size_t)row * Cq;
    float v[4]; float s = 0.f, s2 = 0.f;
    #pragma unroll
    for (int i = 0; i < 4; i++) {
        v[i] = x[off + tid + i*256];
        s += v[i]; s2 += v[i]*v[i];
    }
    block_reduce_2(s, s2);
    float mu = s * (1.f/Cq);
    float inv = rsqrtf(s2*(1.f/Cq) - mu*mu + EPSq);
    float o[4]; s = 0.f; s2 = 0.f;
    #pragma unroll
    for (int i = 0; i < 4; i++) {
        int c = tid + i*256;
        o[i] = (v[i]-mu)*inv*w0[c] + b0[c];
        x0[off + c] = o[i];
        s += o[i]; s2 += o[i]*o[i];
    }
    block_reduce_2(s, s2);
    mu = s * (1.f/Cq);
    inv = rsqrtf(s2*(1.f/Cq) - mu*mu + EPSq);
    #pragma unroll
    for (int i = 0; i < 4; i++) {
        int c = tid + i*256;
        xn[off + c] = (o[i]-mu)*inv*w1[c] + b1[c];
    }
}

__global__ void ln_kernel(const float* __restrict__ x,
                          const float* __restrict__ w, const float* __restrict__ b,
                          float* __restrict__ out) {
    int row = blockIdx.x, tid = threadIdx.x;
    size_t off = (size_t)row * Cq;
    float v[4]; float s = 0.f, s2 = 0.f;
    #pragma unroll
    for (int i = 0; i < 4; i++) {
        v[i] = x[off + tid + i*256];
        s += v[i]; s2 += v[i]*v[i];
    }
    block_reduce_2(s, s2);
    float mu = s * (1.f/Cq);
    float inv = rsqrtf(s2*(1.f/Cq) - mu*mu + EPSq);
    #pragma unroll
    for (int i = 0; i < 4; i++) {
        int c = tid + i*256;
        out[off + c] = (v[i]-mu)*inv*w[c] + b[c];
    }
}

// ---------------- token-shift mixes (emit fp16 hi/lo) -----------------------
__global__ void mix4_kernel(const float* __restrict__ xn,
                            const float* __restrict__ tmk, const float* __restrict__ tmv,
                            const float* __restrict__ tmr, const float* __restrict__ tmg,
                            __half* __restrict__ xkh, __half* __restrict__ xkl,
                            __half* __restrict__ xvh, __half* __restrict__ xvl,
                            __half* __restrict__ xrh, __half* __restrict__ xrl,
                            __half* __restrict__ xgh, __half* __restrict__ xgl) {
    int row = blockIdx.x, tid = threadIdx.x;
    int t = row & (Tq-1);
    size_t off = (size_t)row * Cq;
    #pragma unroll
    for (int i = 0; i < 2; i++) {
        int c = (tid + i*256) * 2;
        float2 cur = *(const float2*)(xn + off + c);
        float2 prv = (t > 0) ? *(const float2*)(xn + off - Cq + c) : make_float2(0.f, 0.f);
        float2 mk = *(const float2*)(tmk + c), mv = *(const float2*)(tmv + c);
        float2 mr = *(const float2*)(tmr + c), mg = *(const float2*)(tmg + c);
        __half h0,l0,h1,l1;
        float a0 = cur.x*mk.x + prv.x*(1.f-mk.x), a1 = cur.y*mk.y + prv.y*(1.f-mk.y);
        split2h(a0,h0,l0); split2h(a1,h1,l1);
        *(uint32_t*)(xkh+off+c) = pack2h(h0,h1); *(uint32_t*)(xkl+off+c) = pack2h(l0,l1);
        a0 = cur.x*mv.x + prv.x*(1.f-mv.x); a1 = cur.y*mv.y + prv.y*(1.f-mv.y);
        split2h(a0,h0,l0); split2h(a1,h1,l1);
        *(uint32_t*)(xvh+off+c) = pack2h(h0,h1); *(uint32_t*)(xvl+off+c) = pack2h(l0,l1);
        a0 = cur.x*mr.x + prv.x*(1.f-mr.x); a1 = cur.y*mr.y + prv.y*(1.f-mr.y);
        split2h(a0,h0,l0); split2h(a1,h1,l1);
        *(uint32_t*)(xrh+off+c) = pack2h(h0,h1); *(uint32_t*)(xrl+off+c) = pack2h(l0,l1);
        a0 = cur.x*mg.x + prv.x*(1.f-mg.x); a1 = cur.y*mg.y + prv.y*(1.f-mg.y);
        split2h(a0,h0,l0); split2h(a1,h1,l1);
        *(uint32_t*)(xgh+off+c) = pack2h(h0,h1); *(uint32_t*)(xgl+off+c) = pack2h(l0,l1);
    }
}

__global__ void mix2_kernel(const float* __restrict__ xn,
                            const float* __restrict__ tmk, const float* __restrict__ tmr,
                            __half* __restrict__ xkh, __half* __restrict__ xkl,
                            __half* __restrict__ xrh, __half* __restrict__ xrl) {
    int row = blockIdx.x, tid = threadIdx.x;
    int t = row & (Tq-1);
    size_t off = (size_t)row * Cq;
    #pragma unroll
    for (int i = 0; i < 2; i++) {
        int c = (tid + i*256) * 2;
        float2 cur = *(const float2*)(xn + off + c);
        float2 prv = (t > 0) ? *(const float2*)(xn + off - Cq + c) : make_float2(0.f, 0.f);
        float2 mk = *(const float2*)(tmk + c), mr = *(const float2*)(tmr + c);
        __half h0,l0,h1,l1;
        float a0 = cur.x*mk.x + prv.x*(1.f-mk.x), a1 = cur.y*mk.y + prv.y*(1.f-mk.y);
        split2h(a0,h0,l0); split2h(a1,h1,l1);
        *(uint32_t*)(xkh+off+c) = pack2h(h0,h1); *(uint32_t*)(xkl+off+c) = pack2h(l0,l1);
        a0 = cur.x*mr.x + prv.x*(1.f-mr.x); a1 = cur.y*mr.y + prv.y*(1.f-mr.y);
        split2h(a0,h0,l0); split2h(a1,h1,l1);
        *(uint32_t*)(xrh+off+c) = pack2h(h0,h1); *(uint32_t*)(xrl+off+c) = pack2h(l0,l1);
    }
}

// ---------------- weight fp32 -> single fp16 ---------------------------------
__global__ void cvt_kernel(const float* __restrict__ in,
                           __half* __restrict__ h, int n4) {
    int i = blockIdx.x * 256 + threadIdx.x;
    if (i >= n4) return;
    float4 v = ((const float4*)in)[i];
    __half h0 = __float2half_rn(v.x), h1 = __float2half_rn(v.y);
    __half h2 = __float2half_rn(v.z), h3 = __float2half_rn(v.w);
    ((uint2*)h)[i] = make_uint2(pack2h(h0,h1), pack2h(h2,h3));
}

// ---------------- wkv5 recurrence (prefetch + single barrier per step) ------
__global__ void __launch_bounds__(256)
wkv5_kernel(const float* __restrict__ r, const float* __restrict__ k,
            const float* __restrict__ v, const float* __restrict__ w,
            const float* __restrict__ u, float* __restrict__ y) {
    int bh = blockIdx.x;
    int b = bh >> 4, h = bh & 15;
    int tid = threadIdx.x;
    int j = tid >> 2, q = tid & 3, i0 = q * 16;

    __shared__ float rs[2][64], ks[2][64], vs[2][64];

    float s[16], ew[16], us[16];
    #pragma unroll
    for (int ii = 0; ii < 16; ii++) {
        s[ii] = 0.f;
        ew[ii] = expf(-expf(w[h*64 + i0 + ii]));
        us[ii] = u[h*64 + i0 + ii];
    }

    size_t base = (size_t)b * Tq * Cq + h * 64;
    float pre = 0.f;
    {
        size_t off0 = base;
        if (tid < 64)        pre = r[off0 + tid];
        else if (tid < 128)  pre = k[off0 + tid - 64];
        else if (tid < 192)  pre = v[off0 + tid - 128];
    }

    for (int t = 0; t < Tq; t++) {
        int bufi = t & 1;
        if (tid < 64)        rs[bufi][tid]      = pre;
        else if (tid < 128)  ks[bufi][tid-64]   = pre;
        else if (tid < 192)  vs[bufi][tid-128]  = pre;
        if (t + 1 < Tq) {
            size_t offn = base + (size_t)(t+1) * Cq;
            if (tid < 64)        pre = r[offn + tid];
            else if (tid < 128)  pre = k[offn + tid - 64];
            else if (tid < 192)  pre = v[offn + tid - 128];
        }
        __syncthreads();

        float vj = vs[bufi][j];
        float yp = 0.f, cs = 0.f;
        #pragma unroll
        for (int ii = 0; ii < 16; ii++) {
            float rv = rs[bufi][i0+ii];
            float kv_ = ks[bufi][i0+ii];
            yp = fmaf(rv, s[ii], yp);
            cs = fmaf(rv * us[ii], kv_, cs);
            s[ii] = fmaf(ew[ii], s[ii], kv_ * vj);
        }
        yp += __shfl_xor_sync(0xffffffffu, yp, 1);
        yp += __shfl_xor_sync(0xffffffffu, yp, 2);
        cs += __shfl_xor_sync(0xffffffffu, cs, 1);
        cs += __shfl_xor_sync(0xffffffffu, cs, 2);
        if (q == 0) y[base + (size_t)t * Cq + j] = yp + cs * vj;
    }
}

// ---------------- groupnorm(y/8)*silu(g) -> z hi/lo fp16 --------------------
__global__ void gngate_kernel(const float* __restrict__ y, const float* __restrict__ g,
                              const float* __restrict__ w, const float* __restrict__ b,
                              __half* __restrict__ zh, __half* __restrict__ zl) {
    int idx = blockIdx.x;              // row*H + h
    int h = idx & (Hq-1);
    size_t off = (size_t)(idx >> 4) * Cq + h * 64;
    int lane = threadIdx.x;
    float y0 = y[off + lane]      * 0.125f;
    float y1 = y[off + lane + 32] * 0.125f;
    float s = y0 + y1, s2 = y0*y0 + y1*y1;
    #pragma unroll
    for (int o = 16; o > 0; o >>= 1) {
        s  += __shfl_xor_sync(0xffffffffu, s, o);
        s2 += __shfl_xor_sync(0xffffffffu, s2, o);
    }
    float mu = s * (1.f/64.f);
    float inv = rsqrtf(s2*(1.f/64.f) - mu*mu + EPSq);
    int c0 = h*64 + lane;
    float g0 = g[off + lane];
    float g1 = g[off + lane + 32];
    float si0 = g0 / (1.f + __expf(-g0));
    float si1 = g1 / (1.f + __expf(-g1));
    float z0 = ((y0-mu)*inv*w[c0]    + b[c0])    * si0;
    float z1 = ((y1-mu)*inv*w[c0+32] + b[c0+32]) * si1;
    __half h0,l0,h1,l1;
    split2h(z0,h0,l0); split2h(z1,h1,l1);
    zh[off + lane]      = h0;  zl[off + lane]      = l0;
    zh[off + lane + 32] = h1;  zl[off + lane + 32] = l1;
}

// ---------------- launch ----------------------------------------------------
extern "C" void kernel_launch(void* const* d_in, const int* in_sizes, int n_in,
                              void* d_out, int out_size) {
    const float* x        = (const float*)d_in[0];
    const float* ln0_w    = (const float*)d_in[1];
    const float* ln0_b    = (const float*)d_in[2];
    const float* ln1_w    = (const float*)d_in[3];
    const float* ln1_b    = (const float*)d_in[4];
    const float* ln2_w    = (const float*)d_in[5];
    const float* ln2_b    = (const float*)d_in[6];
    const float* att_tmk  = (const float*)d_in[7];
    const float* att_tmv  = (const float*)d_in[8];
    const float* att_tmr  = (const float*)d_in[9];
    const float* att_tmg  = (const float*)d_in[10];
    const float* att_decay= (const float*)d_in[11];
    const float* att_faaaa= (const float*)d_in[12];
    const float* att_Wr   = (const float*)d_in[13];
    const float* att_Wk   = (const float*)d_in[14];
    const float* att_Wv   = (const float*)d_in[15];
    const float* att_Wg   = (const float*)d_in[16];
    const float* att_Wo   = (const float*)d_in[17];
    const float* lnx_w    = (const float*)d_in[18];
    const float* lnx_b    = (const float*)d_in[19];
    const float* ffn_tmk  = (const float*)d_in[20];
    const float* ffn_tmr  = (const float*)d_in[21];
    const float* ffn_Wk   = (const float*)d_in[22];
    const float* ffn_Wr   = (const float*)d_in[23];
    const float* ffn_Wv   = (const float*)d_in[24];
    float* out = (float*)d_out;

    float *x0,*xn,*r_,*k_,*v_,*g_,*y_,*x1,*kv;
    cudaGetSymbolAddress((void**)&x0, g_x0);
    cudaGetSymbolAddress((void**)&xn, g_xn);
    cudaGetSymbolAddress((void**)&r_, g_r);
    cudaGetSymbolAddress((void**)&k_, g_k);
    cudaGetSymbolAddress((void**)&v_, g_v);
    cudaGetSymbolAddress((void**)&g_, g_g);
    cudaGetSymbolAddress((void**)&y_, g_y);
    cudaGetSymbolAddress((void**)&x1, g_x1);
    cudaGetSymbolAddress((void**)&kv, g_kv);

    __half *xrh,*xrl,*xkh,*xkl,*xvh,*xvl,*xgh,*xgl,*kfh,*kfl;
    __half *wr,*wk,*wv,*wg,*wo,*fk,*fr,*fv;
    cudaGetSymbolAddress((void**)&xrh, g_xrh); cudaGetSymbolAddress((void**)&xrl, g_xrl);
    cudaGetSymbolAddress((void**)&xkh, g_xkh); cudaGetSymbolAddress((void**)&xkl, g_xkl);
    cudaGetSymbolAddress((void**)&xvh, g_xvh); cudaGetSymbolAddress((void**)&xvl, g_xvl);
    cudaGetSymbolAddress((void**)&xgh, g_xgh); cudaGetSymbolAddress((void**)&xgl, g_xgl);
    cudaGetSymbolAddress((void**)&kfh, g_kfh); cudaGetSymbolAddress((void**)&kfl, g_kfl);
    cudaGetSymbolAddress((void**)&wr, g_wr);
    cudaGetSymbolAddress((void**)&wk, g_wk);
    cudaGetSymbolAddress((void**)&wv, g_wv);
    cudaGetSymbolAddress((void**)&wg, g_wg);
    cudaGetSymbolAddress((void**)&wo, g_wo);
    cudaGetSymbolAddress((void**)&fk, g_fk);
    cudaGetSymbolAddress((void**)&fr, g_fr);
    cudaGetSymbolAddress((void**)&fv, g_fv);

    cudaFuncSetAttribute(gemm_tc<0>, cudaFuncAttributeMaxDynamicSharedMemorySize, GEMM_SMEM);
    cudaFuncSetAttribute(gemm_tc<1>, cudaFuncAttributeMaxDynamicSharedMemorySize, GEMM_SMEM);
    cudaFuncSetAttribute(gemm_tc<2>, cudaFuncAttributeMaxDynamicSharedMemorySize, GEMM_SMEM);
    cudaFuncSetAttribute(gemm_tc<3>, cudaFuncAttributeMaxDynamicSharedMemorySize, GEMM_SMEM);

    dim3 blk256(256);
    const int nCC = Cq*Cq/4, nFC = FFNq*Cq/4;
    dim3 gCC(Cq/128, ROWS/128);       // (8, 128)
    dim3 gCF(FFNq/128, ROWS/128);     // (28, 128)

    cvt_kernel<<<nCC/256, 256>>>(att_Wr, wr, nCC);                             // 0
    ln01_kernel<<<ROWS, blk256>>>(x, ln0_w, ln0_b, ln1_w, ln1_b, x0, xn);      // 1
    mix4_kernel<<<ROWS, blk256>>>(xn, att_tmk, att_tmv, att_tmr, att_tmg,
                                  xkh, xkl, xvh, xvl, xrh, xrl, xgh, xgl);     // 2
    cvt_kernel<<<nCC/256, 256>>>(att_Wk, wk, nCC);                             // 3
    gemm_tc<0><<<gCC, 256, GEMM_SMEM>>>(xrh, xrl, wr, r_, Cq, Cq,
                                        nullptr, nullptr, nullptr, nullptr);   // 4
    gemm_tc<0><<<gCC, 256, GEMM_SMEM>>>(xkh, xkl, wk, k_, Cq, Cq,
                                        nullptr, nullptr, nullptr, nullptr);   // 5
    cvt_kernel<<<nCC/256, 256>>>(att_Wv, wv, nCC);
    cvt_kernel<<<nCC/256, 256>>>(att_Wg, wg, nCC);
    cvt_kernel<<<nCC/256, 256>>>(att_Wo, wo, nCC);
    cvt_kernel<<<nFC/256, 256>>>(ffn_Wk, fk, nFC);
    cvt_kernel<<<nCC/256, 256>>>(ffn_Wr, fr, nCC);
    cvt_kernel<<<nFC/256, 256>>>(ffn_Wv, fv, nFC);

    gemm_tc<0><<<gCC, 256, GEMM_SMEM>>>(xvh, xvl, wv, v_, Cq, Cq, nullptr, nullptr, nullptr, nullptr);
    gemm_tc<0><<<gCC, 256, GEMM_SMEM>>>(xgh, xgl, wg, g_, Cq, Cq, nullptr, nullptr, nullptr, nullptr);
    // wkv5 recurrence
    wkv5_kernel<<<Bq*Hq, blk256>>>(r_, k_, v_, att_decay, att_faaaa, y_);
    // groupnorm + gate -> z hi/lo (reuse xg buffers)
    gngate_kernel<<<ROWS*Hq, 32>>>(y_, g_, lnx_w, lnx_b, xgh, xgl);
    // output projection + residual
    gemm_tc<1><<<gCC, 256, GEMM_SMEM>>>(xgh, xgl, wo, x1, Cq, Cq, x0, nullptr, nullptr, nullptr);
    // channel-mix
    ln_kernel<<<ROWS, blk256>>>(x1, ln2_w, ln2_b, xn);
    mix2_kernel<<<ROWS, blk256>>>(xn, ffn_tmk, ffn_tmr, xkh, xkl, xrh, xrl);
    gemm_tc<2><<<gCF, 256, GEMM_SMEM>>>(xkh, xkl, fk, nullptr, FFNq, Cq, nullptr, nullptr, kfh, kfl);
    gemm_tc<0><<<gCC, 256, GEMM_SMEM>>>(kfh, kfl, fv, kv, Cq, FFNq, nullptr, nullptr, nullptr, nullptr);
    gemm_tc<3><<<gCC, 256, GEMM_SMEM>>>(xrh, xrl, fr, out, Cq, Cq, x1, kv, nullptr, nullptr);
}

// round 17
// speedup vs baseline: 4.5380x; 1.3141x over previous
#include <cuda_runtime.h>
#include <cuda_fp16.h>
#include <cstdint>
#include <math.h>

#define Bq 8
#define Tq 2048
#define Cq 1024
#define Hq 16
#define Nq 64
#define FFNq 3584
#define EPSq 1e-5f
#define ROWS (Bq*Tq)            // 16384

// ---------------- scratch (device globals; no cudaMalloc allowed) -----------
__device__ __align__(16) float g_x0 [ROWS*Cq];
__device__ __align__(16) float g_xn [ROWS*Cq];
__device__ __align__(16) float g_r  [ROWS*Cq];
__device__ __align__(16) float g_k  [ROWS*Cq];
__device__ __align__(16) float g_v  [ROWS*Cq];
__device__ __align__(16) float g_g  [ROWS*Cq];
__device__ __align__(16) float g_y  [ROWS*Cq];
__device__ __align__(16) float g_x1 [ROWS*Cq];
__device__ __align__(16) float g_kv [ROWS*Cq];
// fp16 activations (single precision fp16)
__device__ __align__(16) __half g_xr[ROWS*Cq];
__device__ __align__(16) __half g_xk[ROWS*Cq];
__device__ __align__(16) __half g_xv[ROWS*Cq];
__device__ __align__(16) __half g_xg[ROWS*Cq];     // reused for z
__device__ __align__(16) __half g_kf[(size_t)ROWS*FFNq];
// fp16 weights
__device__ __align__(16) __half g_wr[Cq*Cq];
__device__ __align__(16) __half g_wk[Cq*Cq];
__device__ __align__(16) __half g_wv[Cq*Cq];
__device__ __align__(16) __half g_wg[Cq*Cq];
__device__ __align__(16) __half g_wo[Cq*Cq];
__device__ __align__(16) __half g_fkw[FFNq*Cq];
__device__ __align__(16) __half g_fr[Cq*Cq];
__device__ __align__(16) __half g_fv[Cq*FFNq];

// ---------------- helpers ----------------------------------------------------
__device__ __forceinline__ uint32_t smem_u32(const void* p) {
    uint32_t a;
    asm("{ .reg .u64 t; cvta.to.shared.u64 t, %1; cvt.u32.u64 %0, t; }" : "=r"(a) : "l"(p));
    return a;
}
__device__ __forceinline__ void cp16(uint32_t dst, const void* src) {
    asm volatile("cp.async.cg.shared.global [%0], [%1], 16;" :: "r"(dst), "l"(src) : "memory");
}
__device__ __forceinline__ void cp_commit() {
    asm volatile("cp.async.commit_group;" ::: "memory");
}
template<int N>
__device__ __forceinline__ void cp_wait() {
    asm volatile("cp.async.wait_group %0;" :: "n"(N) : "memory");
}
__device__ __forceinline__ void ldm4(uint32_t* r, uint32_t addr) {
    asm volatile("ldmatrix.sync.aligned.m8n8.x4.shared.b16 {%0,%1,%2,%3}, [%4];"
        : "=r"(r[0]), "=r"(r[1]), "=r"(r[2]), "=r"(r[3]) : "r"(addr));
}
__device__ __forceinline__ void mma16816(float* c, const uint32_t* a, const uint32_t* b) {
    asm volatile("mma.sync.aligned.m16n8k16.row.col.f32.f16.f16.f32 "
        "{%0,%1,%2,%3}, {%4,%5,%6,%7}, {%8,%9}, {%0,%1,%2,%3};"
        : "+f"(c[0]), "+f"(c[1]), "+f"(c[2]), "+f"(c[3])
        : "r"(a[0]), "r"(a[1]), "r"(a[2]), "r"(a[3]), "r"(b[0]), "r"(b[1]));
}
__device__ __forceinline__ uint32_t pack2h(__half a, __half b) {
    return (uint32_t)__half_as_ushort(a) | ((uint32_t)__half_as_ushort(b) << 16);
}

// ---------------- mma.sync fp16 NT GEMM --------------------------------------
// out[m][n] = epi( sum_k A[m][k]*W[n][k] );  A and W single fp16, fp32 accum.
// EPI: 0 plain fp32, 1 res+acc fp32, 2 relu(acc)^2 -> fp16, 3 res+sigmoid(acc)*aux
// CTA 128x128, 256 thr = 2(m) x 4(n) warps, warp 64x32. K-chunk 32 fp16.
#define KC 32
#define PSTR 80                      // padded smem row stride in bytes (40 fp16)
#define MATB (128*PSTR)              // 10240 bytes per matrix tile
#define STAGEB (2*MATB)              // 20480 per stage (A, W)
#define GEMM_SMEM (2*STAGEB)         // 40960

__device__ __forceinline__ void stage_load(
    uint32_t stg, const __half* A, const __half* W,
    int bm, int bn, int K, int k0, int tid)
{
    #pragma unroll
    for (int it = 0; it < 2; it++) {
        int idx = tid * 2 + it;        // 0..511
        int row = idx >> 2, seg = idx & 3;
        uint32_t d = stg + row * PSTR + seg * 16;
        size_t ao = (size_t)(bm + row) * K + k0 + seg * 8;
        size_t bo = (size_t)(bn + row) * K + k0 + seg * 8;
        cp16(d,        A + ao);
        cp16(d + MATB, W + bo);
    }
}

template<int EPI>
__global__ void __launch_bounds__(256, 2)
gemm_tc(const __half* __restrict__ A, const __half* __restrict__ W,
        float* __restrict__ out, int N, int K,
        const float* __restrict__ res, const float* __restrict__ aux,
        __half* __restrict__ out_h)
{
    extern __shared__ __align__(16) char smem[];
    const uint32_t sb = smem_u32(smem);
    const int tid = threadIdx.x;
    const int bm = blockIdx.y * 128, bn = blockIdx.x * 128;
    const int warp = tid >> 5, lane = tid & 31;
    const int wm = warp >> 2, wn = warp & 3;           // 2 x 4 warp grid
    const int r = lane >> 2, c4 = lane & 3;

    float acc[4][4][4];
    #pragma unroll
    for (int i = 0; i < 4; i++)
        #pragma unroll
        for (int j = 0; j < 4; j++)
            #pragma unroll
            for (int q = 0; q < 4; q++) acc[i][j][q] = 0.f;

    const int nchunk = K / KC;
    stage_load(sb, A, W, bm, bn, K, 0, tid);
    cp_commit();

    // ldmatrix lane-address offsets (bytes within a matrix tile)
    const int aRow = wm*64 + (lane & 7) + ((lane >> 3) & 1) * 8;
    const uint32_t aOff = (uint32_t)aRow * PSTR + (lane >> 4) * 16;
    const int bRow = wn*32 + (lane & 7) + (lane >> 4) * 8;
    const uint32_t bOff = (uint32_t)bRow * PSTR + ((lane >> 3) & 1) * 16;

    for (int c = 0; c < nchunk; c++) {
        if (c + 1 < nchunk) {
            stage_load(sb + ((c+1)&1)*STAGEB, A, W, bm, bn, K, (c+1)*KC, tid);
            cp_commit();
            cp_wait<1>();
        } else {
            cp_wait<0>();
        }
        __syncthreads();
        const uint32_t st = sb + (c & 1) * STAGEB;
        #pragma unroll
        for (int ks = 0; ks < 2; ks++) {
            const uint32_t ko = ks * 32;               // 16 fp16 = 32 bytes
            uint32_t bf[4][2];
            #pragma unroll
            for (int ntp = 0; ntp < 2; ntp++) {
                uint32_t t[4];
                ldm4(t, st + MATB + bOff + ntp*16*PSTR + ko);
                bf[2*ntp][0] = t[0]; bf[2*ntp][1] = t[1];
                bf[2*ntp+1][0] = t[2]; bf[2*ntp+1][1] = t[3];
            }
            #pragma unroll
            for (int mt = 0; mt < 4; mt++) {
                uint32_t ah[4];
                ldm4(ah, st + aOff + mt*16*PSTR + ko);
                #pragma unroll
                for (int nt = 0; nt < 4; nt++)
                    mma16816(acc[mt][nt], ah, bf[nt]);
            }
        }
        __syncthreads();
    }

    // epilogue
    #pragma unroll
    for (int mt = 0; mt < 4; mt++) {
        #pragma unroll
        for (int nt = 0; nt < 4; nt++) {
            const int m0 = bm + wm*64 + mt*16 + r;
            const int n0 = bn + wn*32 + nt*8 + c4*2;
            #pragma unroll
            for (int half_ = 0; half_ < 2; half_++) {
                const int m_ = m0 + half_*8;
                const size_t ob = (size_t)m_ * N + n0;
                float v0 = acc[mt][nt][half_*2], v1 = acc[mt][nt][half_*2+1];
                if (EPI == 0) {
                    *(float2*)(out + ob) = make_float2(v0, v1);
                } else if (EPI == 1) {
                    float2 rv = *(const float2*)(res + ob);
                    *(float2*)(out + ob) = make_float2(rv.x + v0, rv.y + v1);
                } else if (EPI == 3) {
                    float2 rv = *(const float2*)(res + ob);
                    float2 av = *(const float2*)(aux + ob);
                    float s0 = 1.f/(1.f + __expf(-v0));
                    float s1 = 1.f/(1.f + __expf(-v1));
                    *(float2*)(out + ob) = make_float2(rv.x + s0*av.x, rv.y + s1*av.y);
                } else { // relu^2 -> fp16
                    float t0 = fmaxf(v0, 0.f); t0 *= t0;
                    float t1 = fmaxf(v1, 0.f); t1 *= t1;
                    *(uint32_t*)(out_h + ob) = pack2h(__float2half_rn(t0), __float2half_rn(t1));
                }
            }
        }
    }
}

// ---------------- block reduce (sum pair) over 256 threads ------------------
__device__ __forceinline__ void block_reduce_2(float& a, float& b) {
    __shared__ float sa[8], sb2[8];
    int lane = threadIdx.x & 31, wid = threadIdx.x >> 5;
    #pragma unroll
    for (int o = 16; o > 0; o >>= 1) {
        a += __shfl_xor_sync(0xffffffffu, a, o);
        b += __shfl_xor_sync(0xffffffffu, b, o);
    }
    if (lane == 0) { sa[wid] = a; sb2[wid] = b; }
    __syncthreads();
    a = 0.f; b = 0.f;
    #pragma unroll
    for (int i = 0; i < 8; i++) { a += sa[i]; b += sb2[i]; }
    __syncthreads();
}

// ---------------- fused ln0 + ln1 -------------------------------------------
__global__ void ln01_kernel(const float* __restrict__ x,
                            const float* __restrict__ w0, const float* __restrict__ b0,
                            const float* __restrict__ w1, const float* __restrict__ b1,
                            float* __restrict__ x0, float* __restrict__ xn) {
    int row = blockIdx.x, tid = threadIdx.x;
    size_t off = (size_t)row * Cq;
    float v[4]; float s = 0.f, s2 = 0.f;
    #pragma unroll
    for (int i = 0; i < 4; i++) {
        v[i] = x[off + tid + i*256];
        s += v[i]; s2 += v[i]*v[i];
    }
    block_reduce_2(s, s2);
    float mu = s * (1.f/Cq);
    float inv = rsqrtf(s2*(1.f/Cq) - mu*mu + EPSq);
    float o[4]; s = 0.f; s2 = 0.f;
    #pragma unroll
    for (int i = 0; i < 4; i++) {
        int c = tid + i*256;
        o[i] = (v[i]-mu)*inv*w0[c] + b0[c];
        x0[off + c] = o[i];
        s += o[i]; s2 += o[i]*o[i];
    }
    block_reduce_2(s, s2);
    mu = s * (1.f/Cq);
    inv = rsqrtf(s2*(1.f/Cq) - mu*mu + EPSq);
    #pragma unroll
    for (int i = 0; i < 4; i++) {
        int c = tid + i*256;
        xn[off + c] = (o[i]-mu)*inv*w1[c] + b1[c];
    }
}

__global__ void ln_kernel(const float* __restrict__ x,
                          const float* __restrict__ w, const float* __restrict__ b,
                          float* __restrict__ out) {
    int row = blockIdx.x, tid = threadIdx.x;
    size_t off = (size_t)row * Cq;
    float v[4]; float s = 0.f, s2 = 0.f;
    #pragma unroll
    for (int i = 0; i < 4; i++) {
        v[i] = x[off + tid + i*256];
        s += v[i]; s2 += v[i]*v[i];
    }
    block_reduce_2(s, s2);
    float mu = s * (1.f/Cq);
    float inv = rsqrtf(s2*(1.f/Cq) - mu*mu + EPSq);
    #pragma unroll
    for (int i = 0; i < 4; i++) {
        int c = tid + i*256;
        out[off + c] = (v[i]-mu)*inv*w[c] + b[c];
    }
}

// ---------------- token-shift mixes (emit fp16) -----------------------------
__global__ void mix4_kernel(const float* __restrict__ xn,
                            const float* __restrict__ tmk, const float* __restrict__ tmv,
                            const float* __restrict__ tmr, const float* __restrict__ tmg,
                            __half* __restrict__ xk, __half* __restrict__ xv,
                            __half* __restrict__ xr, __half* __restrict__ xg) {
    int row = blockIdx.x, tid = threadIdx.x;
    int t = row & (Tq-1);
    size_t off = (size_t)row * Cq;
    #pragma unroll
    for (int i = 0; i < 2; i++) {
        int c = (tid + i*256) * 2;
        float2 cur = *(const float2*)(xn + off + c);
        float2 prv = (t > 0) ? *(const float2*)(xn + off - Cq + c) : make_float2(0.f, 0.f);
        float2 mk = *(const float2*)(tmk + c), mv = *(const float2*)(tmv + c);
        float2 mr = *(const float2*)(tmr + c), mg = *(const float2*)(tmg + c);
        float a0 = cur.x*mk.x + prv.x*(1.f-mk.x), a1 = cur.y*mk.y + prv.y*(1.f-mk.y);
        *(uint32_t*)(xk+off+c) = pack2h(__float2half_rn(a0), __float2half_rn(a1));
        a0 = cur.x*mv.x + prv.x*(1.f-mv.x); a1 = cur.y*mv.y + prv.y*(1.f-mv.y);
        *(uint32_t*)(xv+off+c) = pack2h(__float2half_rn(a0), __float2half_rn(a1));
        a0 = cur.x*mr.x + prv.x*(1.f-mr.x); a1 = cur.y*mr.y + prv.y*(1.f-mr.y);
        *(uint32_t*)(xr+off+c) = pack2h(__float2half_rn(a0), __float2half_rn(a1));
        a0 = cur.x*mg.x + prv.x*(1.f-mg.x); a1 = cur.y*mg.y + prv.y*(1.f-mg.y);
        *(uint32_t*)(xg+off+c) = pack2h(__float2half_rn(a0), __float2half_rn(a1));
    }
}

__global__ void mix2_kernel(const float* __restrict__ xn,
                            const float* __restrict__ tmk, const float* __restrict__ tmr,
                            __half* __restrict__ xk, __half* __restrict__ xr) {
    int row = blockIdx.x, tid = threadIdx.x;
    int t = row & (Tq-1);
    size_t off = (size_t)row * Cq;
    #pragma unroll
    for (int i = 0; i < 2; i++) {
        int c = (tid + i*256) * 2;
        float2 cur = *(const float2*)(xn + off + c);
        float2 prv = (t > 0) ? *(const float2*)(xn + off - Cq + c) : make_float2(0.f, 0.f);
        float2 mk = *(const float2*)(tmk + c), mr = *(const float2*)(tmr + c);
        float a0 = cur.x*mk.x + prv.x*(1.f-mk.x), a1 = cur.y*mk.y + prv.y*(1.f-mk.y);
        *(uint32_t*)(xk+off+c) = pack2h(__float2half_rn(a0), __float2half_rn(a1));
        a0 = cur.x*mr.x + prv.x*(1.f-mr.x); a1 = cur.y*mr.y + prv.y*(1.f-mr.y);
        *(uint32_t*)(xr+off+c) = pack2h(__float2half_rn(a0), __float2half_rn(a1));
    }
}

// ---------------- weight fp32 -> fp16 ----------------------------------------
__global__ void cvt_kernel(const float* __restrict__ in,
                           __half* __restrict__ h, int n4) {
    int i = blockIdx.x * 256 + threadIdx.x;
    if (i >= n4) return;
    float4 v = ((const float4*)in)[i];
    ((uint2*)h)[i] = make_uint2(pack2h(__float2half_rn(v.x), __float2half_rn(v.y)),
                                pack2h(__float2half_rn(v.z), __float2half_rn(v.w)));
}

// ---------------- wkv5 recurrence (prefetch + single barrier per step) ------
__global__ void __launch_bounds__(256)
wkv5_kernel(const float* __restrict__ r, const float* __restrict__ k,
            const float* __restrict__ v, const float* __restrict__ w,
            const float* __restrict__ u, float* __restrict__ y) {
    int bh = blockIdx.x;
    int b = bh >> 4, h = bh & 15;
    int tid = threadIdx.x;
    int j = tid >> 2, q = tid & 3, i0 = q * 16;

    __shared__ float rs[2][64], ks[2][64], vs[2][64];

    float s[16], ew[16], us[16];
    #pragma unroll
    for (int ii = 0; ii < 16; ii++) {
        s[ii] = 0.f;
        ew[ii] = expf(-expf(w[h*64 + i0 + ii]));
        us[ii] = u[h*64 + i0 + ii];
    }

    size_t base = (size_t)b * Tq * Cq + h * 64;
    float pre = 0.f;
    {
        size_t off0 = base;
        if (tid < 64)        pre = r[off0 + tid];
        else if (tid < 128)  pre = k[off0 + tid - 64];
        else if (tid < 192)  pre = v[off0 + tid - 128];
    }

    for (int t = 0; t < Tq; t++) {
        int bufi = t & 1;
        if (tid < 64)        rs[bufi][tid]      = pre;
        else if (tid < 128)  ks[bufi][tid-64]   = pre;
        else if (tid < 192)  vs[bufi][tid-128]  = pre;
        if (t + 1 < Tq) {
            size_t offn = base + (size_t)(t+1) * Cq;
            if (tid < 64)        pre = r[offn + tid];
            else if (tid < 128)  pre = k[offn + tid - 64];
            else if (tid < 192)  pre = v[offn + tid - 128];
        }
        __syncthreads();

        float vj = vs[bufi][j];
        float yp = 0.f, cs = 0.f;
        #pragma unroll
        for (int ii = 0; ii < 16; ii++) {
            float rv = rs[bufi][i0+ii];
            float kv_ = ks[bufi][i0+ii];
            yp = fmaf(rv, s[ii], yp);
            cs = fmaf(rv * us[ii], kv_, cs);
            s[ii] = fmaf(ew[ii], s[ii], kv_ * vj);
        }
        yp += __shfl_xor_sync(0xffffffffu, yp, 1);
        yp += __shfl_xor_sync(0xffffffffu, yp, 2);
        cs += __shfl_xor_sync(0xffffffffu, cs, 1);
        cs += __shfl_xor_sync(0xffffffffu, cs, 2);
        if (q == 0) y[base + (size_t)t * Cq + j] = yp + cs * vj;
    }
}

// ---------------- groupnorm(y/8)*silu(g) -> z fp16 --------------------------
__global__ void gngate_kernel(const float* __restrict__ y, const float* __restrict__ g,
                              const float* __restrict__ w, const float* __restrict__ b,
                              __half* __restrict__ zh) {
    int idx = blockIdx.x;              // row*H + h
    int h = idx & (Hq-1);
    size_t off = (size_t)(idx >> 4) * Cq + h * 64;
    int lane = threadIdx.x;
    float y0 = y[off + lane]      * 0.125f;
    float y1 = y[off + lane + 32] * 0.125f;
    float s = y0 + y1, s2 = y0*y0 + y1*y1;
    #pragma unroll
    for (int o = 16; o > 0; o >>= 1) {
        s  += __shfl_xor_sync(0xffffffffu, s, o);
        s2 += __shfl_xor_sync(0xffffffffu, s2, o);
    }
    float mu = s * (1.f/64.f);
    float inv = rsqrtf(s2*(1.f/64.f) - mu*mu + EPSq);
    int c0 = h*64 + lane;
    float g0 = g[off + lane];
    float g1 = g[off + lane + 32];
    float si0 = g0 / (1.f + __expf(-g0));
    float si1 = g1 / (1.f + __expf(-g1));
    float z0 = ((y0-mu)*inv*w[c0]    + b[c0])    * si0;
    float z1 = ((y1-mu)*inv*w[c0+32] + b[c0+32]) * si1;
    zh[off + lane]      = __float2half_rn(z0);
    zh[off + lane + 32] = __float2half_rn(z1);
}

// ---------------- launch ----------------------------------------------------
extern "C" void kernel_launch(void* const* d_in, const int* in_sizes, int n_in,
                              void* d_out, int out_size) {
    const float* x        = (const float*)d_in[0];
    const float* ln0_w    = (const float*)d_in[1];
    const float* ln0_b    = (const float*)d_in[2];
    const float* ln1_w    = (const float*)d_in[3];
    const float* ln1_b    = (const float*)d_in[4];
    const float* ln2_w    = (const float*)d_in[5];
    const float* ln2_b    = (const float*)d_in[6];
    const float* att_tmk  = (const float*)d_in[7];
    const float* att_tmv  = (const float*)d_in[8];
    const float* att_tmr  = (const float*)d_in[9];
    const float* att_tmg  = (const float*)d_in[10];
    const float* att_decay= (const float*)d_in[11];
    const float* att_faaaa= (const float*)d_in[12];
    const float* att_Wr   = (const float*)d_in[13];
    const float* att_Wk   = (const float*)d_in[14];
    const float* att_Wv   = (const float*)d_in[15];
    const float* att_Wg   = (const float*)d_in[16];
    const float* att_Wo   = (const float*)d_in[17];
    const float* lnx_w    = (const float*)d_in[18];
    const float* lnx_b    = (const float*)d_in[19];
    const float* ffn_tmk  = (const float*)d_in[20];
    const float* ffn_tmr  = (const float*)d_in[21];
    const float* ffn_Wk   = (const float*)d_in[22];
    const float* ffn_Wr   = (const float*)d_in[23];
    const float* ffn_Wv   = (const float*)d_in[24];
    float* out = (float*)d_out;

    float *x0,*xn,*r_,*k_,*v_,*g_,*y_,*x1,*kv;
    cudaGetSymbolAddress((void**)&x0, g_x0);
    cudaGetSymbolAddress((void**)&xn, g_xn);
    cudaGetSymbolAddress((void**)&r_, g_r);
    cudaGetSymbolAddress((void**)&k_, g_k);
    cudaGetSymbolAddress((void**)&v_, g_v);
    cudaGetSymbolAddress((void**)&g_, g_g);
    cudaGetSymbolAddress((void**)&y_, g_y);
    cudaGetSymbolAddress((void**)&x1, g_x1);
    cudaGetSymbolAddress((void**)&kv, g_kv);

    __half *xr,*xk,*xv,*xg,*kf;
    __half *wr,*wk,*wv,*wg,*wo,*fk,*fr,*fv;
    cudaGetSymbolAddress((void**)&xr, g_xr);
    cudaGetSymbolAddress((void**)&xk, g_xk);
    cudaGetSymbolAddress((void**)&xv, g_xv);
    cudaGetSymbolAddress((void**)&xg, g_xg);
    cudaGetSymbolAddress((void**)&kf, g_kf);
    cudaGetSymbolAddress((void**)&wr, g_wr);
    cudaGetSymbolAddress((void**)&wk, g_wk);
    cudaGetSymbolAddress((void**)&wv, g_wv);
    cudaGetSymbolAddress((void**)&wg, g_wg);
    cudaGetSymbolAddress((void**)&wo, g_wo);
    cudaGetSymbolAddress((void**)&fk, g_fkw);
    cudaGetSymbolAddress((void**)&fr, g_fr);
    cudaGetSymbolAddress((void**)&fv, g_fv);

    cudaFuncSetAttribute(gemm_tc<0>, cudaFuncAttributeMaxDynamicSharedMemorySize, GEMM_SMEM);
    cudaFuncSetAttribute(gemm_tc<1>, cudaFuncAttributeMaxDynamicSharedMemorySize, GEMM_SMEM);
    cudaFuncSetAttribute(gemm_tc<2>, cudaFuncAttributeMaxDynamicSharedMemorySize, GEMM_SMEM);
    cudaFuncSetAttribute(gemm_tc<3>, cudaFuncAttributeMaxDynamicSharedMemorySize, GEMM_SMEM);

    dim3 blk256(256);
    const int nCC = Cq*Cq/4, nFC = FFNq*Cq/4;
    dim3 gCC(Cq/128, ROWS/128);       // (8, 128)
    dim3 gCF(FFNq/128, ROWS/128);     // (28, 128)

    cvt_kernel<<<nCC/256, 256>>>(att_Wr, wr, nCC);                             // 0
    ln01_kernel<<<ROWS, blk256>>>(x, ln0_w, ln0_b, ln1_w, ln1_b, x0, xn);      // 1
    mix4_kernel<<<ROWS, blk256>>>(xn, att_tmk, att_tmv, att_tmr, att_tmg,
                                  xk, xv, xr, xg);                             // 2
    cvt_kernel<<<nCC/256, 256>>>(att_Wk, wk, nCC);                             // 3
    gemm_tc<0><<<gCC, 256, GEMM_SMEM>>>(xr, wr, r_, Cq, Cq,
                                        nullptr, nullptr, nullptr);            // 4
    gemm_tc<0><<<gCC, 256, GEMM_SMEM>>>(xk, wk, k_, Cq, Cq,
                                        nullptr, nullptr, nullptr);            // 5
    cvt_kernel<<<nCC/256, 256>>>(att_Wv, wv, nCC);
    cvt_kernel<<<nCC/256, 256>>>(att_Wg, wg, nCC);
    cvt_kernel<<<nCC/256, 256>>>(att_Wo, wo, nCC);
    cvt_kernel<<<nFC/256, 256>>>(ffn_Wk, fk, nFC);
    cvt_kernel<<<nCC/256, 256>>>(ffn_Wr, fr, nCC);
    cvt_kernel<<<nFC/256, 256>>>(ffn_Wv, fv, nFC);

    gemm_tc<0><<<gCC, 256, GEMM_SMEM>>>(xv, wv, v_, Cq, Cq, nullptr, nullptr, nullptr);
    gemm_tc<0><<<gCC, 256, GEMM_SMEM>>>(xg, wg, g_, Cq, Cq, nullptr, nullptr, nullptr);
    // wkv5 recurrence
    wkv5_kernel<<<Bq*Hq, blk256>>>(r_, k_, v_, att_decay, att_faaaa, y_);
    // groupnorm + gate -> z fp16 (reuse xg buffer)
    gngate_kernel<<<ROWS*Hq, 32>>>(y_, g_, lnx_w, lnx_b, xg);
    // output projection + residual
    gemm_tc<1><<<gCC, 256, GEMM_SMEM>>>(xg, wo, x1, Cq, Cq, x0, nullptr, nullptr);
    // channel-mix
    ln_kernel<<<ROWS, blk256>>>(x1, ln2_w, ln2_b, xn);
    mix2_kernel<<<ROWS, blk256>>>(xn, ffn_tmk, ffn_tmr, xk, xr);
    gemm_tc<2><<<gCF, 256, GEMM_SMEM>>>(xk, fk, nullptr, FFNq, Cq, nullptr, nullptr, kf);
    gemm_tc<0><<<gCC, 256, GEMM_SMEM>>>(kf, fv, kv, Cq, FFNq, nullptr, nullptr, nullptr);
    gemm_tc<3><<<gCC, 256, GEMM_SMEM>>>(xr, fr, out, Cq, Cq, x1, kv, nullptr);
}